// round 1
// baseline (speedup 1.0000x reference)
#include <cuda_runtime.h>
#include <cuda_bf16.h>

// Problem constants
#define SEQ   2048
#define BATCH 16
#define DIN   512
#define HID   512
#define MROWS (SEQ*BATCH)       // 32768
#define NCOLS (3*HID*2)         // 3072
#define KDIM  DIN               // 512

// 402MB scratch for g = X @ W^T (raw pre-activation), layout [MROWS][NCOLS]
__device__ float g_G[(size_t)MROWS * NCOLS];

// ---------------------------------------------------------------------------
// Helpers
// ---------------------------------------------------------------------------
__device__ __forceinline__ float to_tf32(float x) {
    unsigned u;
    asm("cvt.rna.tf32.f32 %0, %1;" : "=r"(u) : "f"(x));
    return __uint_as_float(u);
}

__device__ __forceinline__ void mma_tf32(float c[4], const unsigned a[4], const unsigned b[2]) {
    asm volatile(
        "mma.sync.aligned.m16n8k8.row.col.f32.tf32.tf32.f32 "
        "{%0,%1,%2,%3}, {%4,%5,%6,%7}, {%8,%9}, {%0,%1,%2,%3};"
        : "+f"(c[0]), "+f"(c[1]), "+f"(c[2]), "+f"(c[3])
        : "r"(a[0]), "r"(a[1]), "r"(a[2]), "r"(a[3]), "r"(b[0]), "r"(b[1]));
}

__device__ __forceinline__ float ex2f(float x) {
    float y; asm("ex2.approx.ftz.f32 %0, %1;" : "=f"(y) : "f"(x)); return y;
}
__device__ __forceinline__ float rcpf(float x) {
    float y; asm("rcp.approx.ftz.f32 %0, %1;" : "=f"(y) : "f"(x)); return y;
}
// sigmoid(x) = 1 / (1 + 2^(-x*log2e))
__device__ __forceinline__ float sigm_(float x) {
    return rcpf(1.0f + ex2f(-1.4426950408889634f * x));
}
// tanh(x) = 2/(1 + 2^(-2x*log2e)) - 1
__device__ __forceinline__ float tanh_(float x) {
    return fmaf(2.0f, rcpf(1.0f + ex2f(-2.8853900817779268f * x)), -1.0f);
}

// ---------------------------------------------------------------------------
// GEMM: G[m][n] = sum_k X[m][k] * W[n][k]
//   W rows: n in [0,1536) -> W_fw[n], n in [1536,3072) -> W_bw[n-1536]
//   tf32 mma, 128x128x32 block tile, 8 warps (4x2), warp tile 32x64
// ---------------------------------------------------------------------------
#define BM 128
#define BN 128
#define BK 32
#define SPAD 36   // 32 + 4 padding (conflict-free frag loads)

__global__ __launch_bounds__(256) void gemm_tf32_kernel(
    const float* __restrict__ X,
    const float* __restrict__ Wfw,
    const float* __restrict__ Wbw)
{
    __shared__ float sA[BM][SPAD];
    __shared__ float sB[BN][SPAD];

    const int tid  = threadIdx.x;
    const int n0   = blockIdx.x * BN;
    const int m0   = blockIdx.y * BM;

    const float* Asrc = X + (size_t)m0 * KDIM;
    const float* Bsrc = (n0 < 1536) ? (Wfw + (size_t)n0 * KDIM)
                                    : (Wbw + (size_t)(n0 - 1536) * KDIM);

    const int warp = tid >> 5;
    const int lane = tid & 31;
    const int wm   = warp >> 1;     // 0..3
    const int wn   = warp & 1;      // 0..1
    const int lr   = lane >> 2;     // 0..7
    const int lc   = lane & 3;      // 0..3

    float4 ra[4], rb[4];

    // ---- prologue: load k-tile 0 ----
#pragma unroll
    for (int i = 0; i < 4; i++) {
        int slot = tid + i * 256;         // 0..1023
        int row  = slot >> 3;             // 0..127
        int c4   = slot & 7;              // 0..7
        ra[i] = *(const float4*)(Asrc + (size_t)row * KDIM + c4 * 4);
        rb[i] = *(const float4*)(Bsrc + (size_t)row * KDIM + c4 * 4);
    }
#pragma unroll
    for (int i = 0; i < 4; i++) {
        int slot = tid + i * 256;
        int row  = slot >> 3;
        int c4   = slot & 7;
        float4 a = ra[i], b = rb[i];
        a.x = to_tf32(a.x); a.y = to_tf32(a.y); a.z = to_tf32(a.z); a.w = to_tf32(a.w);
        b.x = to_tf32(b.x); b.y = to_tf32(b.y); b.z = to_tf32(b.z); b.w = to_tf32(b.w);
        *(float4*)&sA[row][c4 * 4] = a;
        *(float4*)&sB[row][c4 * 4] = b;
    }
    __syncthreads();

    float acc[2][8][4];
#pragma unroll
    for (int mt = 0; mt < 2; mt++)
#pragma unroll
        for (int nt = 0; nt < 8; nt++)
#pragma unroll
            for (int r = 0; r < 4; r++) acc[mt][nt][r] = 0.0f;

    const int NK = KDIM / BK;  // 16
    for (int kt = 0; kt < NK; kt++) {
        // prefetch next k-tile into registers (overlaps with compute)
        if (kt < NK - 1) {
#pragma unroll
            for (int i = 0; i < 4; i++) {
                int slot = tid + i * 256;
                int row  = slot >> 3;
                int c4   = slot & 7;
                ra[i] = *(const float4*)(Asrc + (size_t)row * KDIM + (kt + 1) * BK + c4 * 4);
                rb[i] = *(const float4*)(Bsrc + (size_t)row * KDIM + (kt + 1) * BK + c4 * 4);
            }
        }

        // compute 4 k-slices of 8 from smem
#pragma unroll
        for (int ks = 0; ks < 4; ks++) {
            unsigned afr[2][4];
            unsigned bfr[8][2];
#pragma unroll
            for (int mt = 0; mt < 2; mt++) {
                int r = wm * 32 + mt * 16 + lr;
                afr[mt][0] = __float_as_uint(sA[r    ][ks * 8 + lc    ]);
                afr[mt][1] = __float_as_uint(sA[r + 8][ks * 8 + lc    ]);
                afr[mt][2] = __float_as_uint(sA[r    ][ks * 8 + lc + 4]);
                afr[mt][3] = __float_as_uint(sA[r + 8][ks * 8 + lc + 4]);
            }
#pragma unroll
            for (int nt = 0; nt < 8; nt++) {
                int nr = wn * 64 + nt * 8 + lr;
                bfr[nt][0] = __float_as_uint(sB[nr][ks * 8 + lc    ]);
                bfr[nt][1] = __float_as_uint(sB[nr][ks * 8 + lc + 4]);
            }
#pragma unroll
            for (int mt = 0; mt < 2; mt++)
#pragma unroll
                for (int nt = 0; nt < 8; nt++)
                    mma_tf32(acc[mt][nt], afr[mt], bfr[nt]);
        }

        __syncthreads();  // smem consumed
        if (kt < NK - 1) {
#pragma unroll
            for (int i = 0; i < 4; i++) {
                int slot = tid + i * 256;
                int row  = slot >> 3;
                int c4   = slot & 7;
                float4 a = ra[i], b = rb[i];
                a.x = to_tf32(a.x); a.y = to_tf32(a.y); a.z = to_tf32(a.z); a.w = to_tf32(a.w);
                b.x = to_tf32(b.x); b.y = to_tf32(b.y); b.z = to_tf32(b.z); b.w = to_tf32(b.w);
                *(float4*)&sA[row][c4 * 4] = a;
                *(float4*)&sB[row][c4 * 4] = b;
            }
            __syncthreads();
        }
    }

    // epilogue: raw g to scratch (bias + activations applied in scan kernel)
#pragma unroll
    for (int mt = 0; mt < 2; mt++) {
#pragma unroll
        for (int nt = 0; nt < 8; nt++) {
            int r0  = m0 + wm * 32 + mt * 16 + lr;
            int col = n0 + wn * 64 + nt * 8 + lc * 2;
            float2 v0 = make_float2(acc[mt][nt][0], acc[mt][nt][1]);
            float2 v1 = make_float2(acc[mt][nt][2], acc[mt][nt][3]);
            *(float2*)(g_G + (size_t)r0 * NCOLS + col)       = v0;
            *(float2*)(g_G + (size_t)(r0 + 8) * NCOLS + col) = v1;
        }
    }
}

// ---------------------------------------------------------------------------
// Scan: one thread per (dir, batch, hid) lane. fw walks s ascending, bw walks
// s descending (equivalent to scanning flip(X) and flipping the result back).
// Chunk-8 register prefetch: 24 independent LDGs in flight per thread.
// ---------------------------------------------------------------------------
__global__ __launch_bounds__(256) void scan_kernel(
    const float* __restrict__ bfw,
    const float* __restrict__ bbw,
    float* __restrict__ Y)
{
    const int c   = blockIdx.x * 256 + threadIdx.x;   // 0..16383
    const int dir = c >> 13;                          // 0 fw, 1 bw
    const int rem = c & 8191;
    const int bi  = rem >> 9;                         // 0..15
    const int h   = rem & 511;

    const float* bias = dir ? bbw : bfw;
    const float bz = bias[h];
    const float bf = bias[HID + h];
    const float bo = bias[2 * HID + h];

    const long long step  = dir ? -(long long)(BATCH * NCOLS) : (long long)(BATCH * NCOLS);
    const long long ystep = dir ? -(long long)(BATCH * 2 * HID) : (long long)(BATCH * 2 * HID);
    const int s0 = dir ? (SEQ - 1) : 0;

    const float* gp = g_G + ((long long)(s0 * BATCH + bi)) * NCOLS + dir * 3 * HID + h;
    float*       yp = Y   + ((long long)(s0 * BATCH + bi)) * (2 * HID) + dir * HID + h;

    float zc[8], fc[8], oc[8];
#pragma unroll
    for (int j = 0; j < 8; j++) {
        zc[j] = gp[0];
        fc[j] = gp[HID];
        oc[j] = gp[2 * HID];
        gp += step;
    }

    float hs = 0.0f;
    const int NCH = SEQ / 8;  // 256
    for (int ch = 0; ch < NCH; ch++) {
        float zn[8], fn[8], on[8];
        if (ch < NCH - 1) {
#pragma unroll
            for (int j = 0; j < 8; j++) {
                zn[j] = gp[0];
                fn[j] = gp[HID];
                on[j] = gp[2 * HID];
                gp += step;
            }
        }
#pragma unroll
        for (int j = 0; j < 8; j++) {
            float z = tanh_(zc[j] + bz);
            float f = sigm_(fc[j] + bf);
            float o = sigm_(oc[j] + bo);
            // h = f*z + (1-f)*h  ==  h + f*(z-h)
            hs = fmaf(f, z - hs, hs);
            yp[0] = o * hs;
            yp += ystep;
        }
#pragma unroll
        for (int j = 0; j < 8; j++) { zc[j] = zn[j]; fc[j] = fn[j]; oc[j] = on[j]; }
    }
}

// ---------------------------------------------------------------------------
// Launch
// ---------------------------------------------------------------------------
extern "C" void kernel_launch(void* const* d_in, const int* in_sizes, int n_in,
                              void* d_out, int out_size)
{
    const float* X   = (const float*)d_in[0];
    const float* Wfw = (const float*)d_in[1];
    const float* bfw = (const float*)d_in[2];
    const float* Wbw = (const float*)d_in[3];
    const float* bbw = (const float*)d_in[4];
    float* Y = (float*)d_out;

    dim3 ggrid(NCOLS / BN, MROWS / BM);   // (24, 256) — x fastest keeps same-M blocks concurrent (X reuse in L2)
    gemm_tf32_kernel<<<ggrid, 256>>>(X, Wfw, Wbw);

    scan_kernel<<<16384 / 256, 256>>>(bfw, bbw, Y);
}

// round 3
// speedup vs baseline: 3.5711x; 3.5711x over previous
#include <cuda_runtime.h>
#include <cuda_fp16.h>
#include <cuda_bf16.h>
#include <cstdint>

// ---------------------------------------------------------------------------
// Problem constants
// ---------------------------------------------------------------------------
#define SEQ   2048
#define BATCH 16
#define DIN   512
#define HID   512
#define MROWS (SEQ*BATCH)       // 32768
#define NCOLS (3*HID*2)         // 3072
#define KDIM  DIN               // 512

// Feature gate: tcgen05 only exists in an arch-specific (sm_103a/sm_100a) pass.
#if defined(__CUDA_ARCH__) && (defined(__CUDA_ARCH_FEAT_SM103_ALL) || defined(__CUDA_ARCH_FEAT_SM100_ALL))
#define HAS_TCGEN05 1
#else
#define HAS_TCGEN05 0
#endif

// Scratch (static device arrays; no allocation allowed)
__device__ float  g_G[(size_t)MROWS * NCOLS];   // raw pre-activation gates (fp32)
__device__ __half g_Xh[(size_t)MROWS * KDIM];   // X in fp16
__device__ __half g_Wh[(size_t)NCOLS * KDIM];   // [W_fw; W_bw] in fp16

// Chunked-scan aggregates: 16384 lanes x 8 chunks, layout [chunk][lane]
#define NLANE 16384
#define NCHK  8
#define CHLEN (SEQ / NCHK)      // 256
__device__ float g_A[NCHK * NLANE];
__device__ float g_C[NCHK * NLANE];
__device__ float g_Hin[NCHK * NLANE];

// ---------------------------------------------------------------------------
// Probe kernel: static smem size tells the host whether the loaded device
// code came from the arch-specific (tcgen05-capable) pass.
// ---------------------------------------------------------------------------
__global__ void probe_kernel(float* p) {
#if HAS_TCGEN05
    __shared__ volatile float s[2048];
#else
    __shared__ volatile float s[64];
#endif
    s[threadIdx.x & 63] = p[0];
    p[1] = s[(threadIdx.x + 1) & 63];
}

// ---------------------------------------------------------------------------
// Common helpers
// ---------------------------------------------------------------------------
__device__ __forceinline__ uint32_t smem_to_u32(const void* p) {
    uint32_t a;
    asm("{ .reg .u64 t; cvta.to.shared.u64 t, %1; cvt.u32.u64 %0, t; }" : "=r"(a) : "l"(p));
    return a;
}

__device__ __forceinline__ float ex2f(float x) {
    float y; asm("ex2.approx.ftz.f32 %0, %1;" : "=f"(y) : "f"(x)); return y;
}
__device__ __forceinline__ float rcpf(float x) {
    float y; asm("rcp.approx.ftz.f32 %0, %1;" : "=f"(y) : "f"(x)); return y;
}
__device__ __forceinline__ float sigm_(float x) {
    return rcpf(1.0f + ex2f(-1.4426950408889634f * x));
}
__device__ __forceinline__ float tanh_(float x) {
    return fmaf(2.0f, rcpf(1.0f + ex2f(-2.8853900817779268f * x)), -1.0f);
}

// ---------------------------------------------------------------------------
// Kernel 0: fp32 -> fp16 conversion (X, W_fw, W_bw)
// ---------------------------------------------------------------------------
__global__ __launch_bounds__(256) void cvt_kernel(
    const float* __restrict__ X,
    const float* __restrict__ Wfw,
    const float* __restrict__ Wbw)
{
    const long long NX = (long long)MROWS * KDIM;     // 16777216
    const long long NW = (long long)(3 * HID) * KDIM; // 786432 per direction
    long long i = ((long long)blockIdx.x * blockDim.x + threadIdx.x) * 4;

    const float* src;
    __half* dst;
    if (i < NX)           { src = X   + i;             dst = g_Xh + i; }
    else if (i < NX + NW) { src = Wfw + (i - NX);      dst = g_Wh + (i - NX); }
    else                  { src = Wbw + (i - NX - NW); dst = g_Wh + (i - NX); }

    float4 v = *(const float4*)src;
    *(__half2*)dst       = __floats2half2_rn(v.x, v.y);
    *(__half2*)(dst + 2) = __floats2half2_rn(v.z, v.w);
}

// ===========================================================================
// GEMM path A: tcgen05 (only present in arch-specific pass)
// ===========================================================================
#define GBM 128
#define GBN 128
#define GBK 64
#define NKCH (KDIM / GBK)        // 8
#define STAGES 3
#define STAGE_BYTES (GBM * 128)  // 16384 per operand per stage
#define SMEM_A_OFF 1024
#define SMEM_B_OFF (1024 + STAGES * STAGE_BYTES)
#define GEMM_SMEM  (1024 + 2 * STAGES * STAGE_BYTES)   // 99328
#define N_MTILE (MROWS / GBM)    // 256
#define N_NTILE (NCOLS / GBN)    // 24
#define N_TILES (N_MTILE * N_NTILE)  // 6144
#define GEMM_CTAS 296

#if HAS_TCGEN05
#define SMEM_SWIZZLE_128B(o) ((o) ^ (((o) >> 3) & 0x70))

static constexpr uint64_t SMEM_DESC_BASE_SW128 =
    (uint64_t(2) << 61) | (uint64_t(1) << 46) | (uint64_t(64) << 32) | (uint64_t(1) << 16);
#define MAKE_SMEM_DESC(base_addr) \
    (SMEM_DESC_BASE_SW128 | ((uint64_t)((base_addr) >> 4) & 0x3FFF))

#define MBARRIER_INIT(addr, cnt) \
    asm volatile("mbarrier.init.shared.b64 [%0], %1;" :: "r"((uint32_t)(addr)), "r"((uint32_t)(cnt)) : "memory")

#define MBARRIER_WAIT_PARITY(mbar_smem_addr, phase_parity) do { \
    uint32_t _mbar = (uint32_t)(mbar_smem_addr); \
    uint32_t _parity = (uint32_t)(phase_parity); \
    uint32_t _done; \
    asm volatile( \
        "{\n\t.reg .pred p;\n\t" \
        "mbarrier.try_wait.parity.acquire.cta.shared::cta.b64 p, [%1], %2;\n\t" \
        "selp.b32 %0, 1, 0, p;\n\t}" \
        : "=r"(_done) : "r"(_mbar), "r"(_parity) : "memory"); \
    if (!_done) { \
        asm volatile( \
            "{\n\t.reg .pred P1;\n\t" \
            "WAIT_LOOP_%=:\n\t" \
            "mbarrier.try_wait.parity.acquire.cta.shared::cta.b64 P1, [%0], %1, 0x989680;\n\t" \
            "@P1 bra.uni WAIT_DONE_%=;\n\t" \
            "bra.uni WAIT_LOOP_%=;\n\t" \
            "WAIT_DONE_%=:\n\t}" \
            :: "r"(_mbar), "r"(_parity) : "memory"); \
    } \
} while(0)

__device__ __forceinline__ uint32_t elect_one_pred() {
    uint32_t pred;
    asm volatile(
        "{\n\t.reg .pred p;\n\t"
        "elect.sync _|p, 0xFFFFFFFF;\n\t"
        "selp.b32 %0, 1, 0, p;\n\t}"
        : "=r"(pred));
    return pred;
}

#define TCGEN05_LD_32X32B_X32(r, tmem_addr) \
    asm volatile( \
        "tcgen05.ld.sync.aligned.32x32b.x32.b32 " \
        "{%0, %1, %2, %3, %4, %5, %6, %7, " \
        " %8, %9, %10, %11, %12, %13, %14, %15, " \
        " %16, %17, %18, %19, %20, %21, %22, %23, " \
        " %24, %25, %26, %27, %28, %29, %30, %31}, [%32];" \
        : "=r"((r)[0]),  "=r"((r)[1]),  "=r"((r)[2]),  "=r"((r)[3]), \
          "=r"((r)[4]),  "=r"((r)[5]),  "=r"((r)[6]),  "=r"((r)[7]), \
          "=r"((r)[8]),  "=r"((r)[9]),  "=r"((r)[10]), "=r"((r)[11]), \
          "=r"((r)[12]), "=r"((r)[13]), "=r"((r)[14]), "=r"((r)[15]), \
          "=r"((r)[16]), "=r"((r)[17]), "=r"((r)[18]), "=r"((r)[19]), \
          "=r"((r)[20]), "=r"((r)[21]), "=r"((r)[22]), "=r"((r)[23]), \
          "=r"((r)[24]), "=r"((r)[25]), "=r"((r)[26]), "=r"((r)[27]), \
          "=r"((r)[28]), "=r"((r)[29]), "=r"((r)[30]), "=r"((r)[31]) \
        : "r"(tmem_addr))

// idesc: dtype=F32 (1<<4), atype=btype=F16 (0), N/8<<17, M/16<<24
#define IDESC_F16 ((1u << 4) | ((GBN / 8u) << 17) | ((GBM / 16u) << 24))

__device__ __forceinline__ void mma_f16_ss(uint32_t d_tmem, uint64_t a_desc, uint64_t b_desc,
                                           uint32_t idesc, bool accum) {
    uint32_t en = accum ? 1u : 0u;
    asm volatile(
        "{\n\t.reg .pred p;\n\t"
        "setp.ne.u32 p, %4, 0;\n\t"
        "tcgen05.mma.cta_group::1.kind::f16 [%0], %1, %2, %3, {%5, %5, %5, %5}, p;\n\t}"
        :: "r"(d_tmem), "l"(a_desc), "l"(b_desc), "r"(idesc), "r"(en), "r"(0u)
        : "memory");
}

__device__ __forceinline__ void cp_async16(uint32_t dst, const void* src) {
    asm volatile("cp.async.cg.shared.global [%0], [%1], 16;" :: "r"(dst), "l"(src) : "memory");
}
__device__ __forceinline__ void cp_commit() {
    asm volatile("cp.async.commit_group;" ::: "memory");
}
template<int N> __device__ __forceinline__ void cp_wait() {
    asm volatile("cp.async.wait_group %0;" :: "n"(N) : "memory");
}

__device__ __forceinline__ void load_stage(uint32_t smem_base, int st, int kt,
                                           int m0, int n0, int tid)
{
    const __half* Asrc = g_Xh + (size_t)m0 * KDIM + kt * GBK;
    const __half* Bsrc = g_Wh + (size_t)n0 * KDIM + kt * GBK;
    uint32_t abase = smem_base + SMEM_A_OFF + st * STAGE_BYTES;
    uint32_t bbase = smem_base + SMEM_B_OFF + st * STAGE_BYTES;
#pragma unroll
    for (int i = 0; i < 8; i++) {
        int chunk = i * 128 + tid;        // 0..1023
        int row   = chunk >> 3;           // 0..127
        int c16   = chunk & 7;            // 16B column chunk
        uint32_t off = SMEM_SWIZZLE_128B((uint32_t)(row * 128 + c16 * 16));
        cp_async16(abase + off, Asrc + (size_t)row * KDIM + c16 * 8);
        cp_async16(bbase + off, Bsrc + (size_t)row * KDIM + c16 * 8);
    }
    cp_commit();
}
#endif  // HAS_TCGEN05

#define MBAR(s) (smem_base + 16 + (s) * 8)

__global__ void __launch_bounds__(128, 2) __cluster_dims__(1, 1, 1) gemm_tc_kernel()
{
#if HAS_TCGEN05
    extern __shared__ char smem[];
    uint32_t smem_base = smem_to_u32(smem);
    const int tid = threadIdx.x;
    const int wid = tid >> 5;
    const int lid = tid & 31;

    if (tid < STAGES) MBARRIER_INIT(MBAR(tid), 1);
    if (wid == 0) {
        asm volatile("tcgen05.alloc.cta_group::1.sync.aligned.shared::cta.b32 [%0], %1;"
            :: "r"(smem_base), "r"(128u) : "memory");
        asm volatile("tcgen05.relinquish_alloc_permit.cta_group::1.sync.aligned;");
    }
    __syncthreads();

    uint32_t tmem;
    asm volatile("ld.shared.b32 %0, [%1];" : "=r"(tmem) : "r"(smem_base));

    int ph0 = 0, ph1 = 0, ph2 = 0;

    for (int tile = blockIdx.x; tile < N_TILES; tile += GEMM_CTAS) {
        const int m0 = (tile / N_NTILE) * GBM;
        const int n0 = (tile % N_NTILE) * GBN;

        load_stage(smem_base, 0, 0, m0, n0, tid);
        load_stage(smem_base, 1, 1, m0, n0, tid);

#pragma unroll
        for (int kt = 0; kt < NKCH; kt++) {
            const int st = kt % STAGES;
            if (kt == NKCH - 1) cp_wait<0>(); else cp_wait<1>();
            __syncthreads();
            asm volatile("fence.proxy.async.shared::cta;" ::: "memory");

            if (wid == 0) {
                if (elect_one_pred()) {
                    uint64_t ad = MAKE_SMEM_DESC(smem_base + SMEM_A_OFF + st * STAGE_BYTES);
                    uint64_t bd = MAKE_SMEM_DESC(smem_base + SMEM_B_OFF + st * STAGE_BYTES);
#pragma unroll
                    for (int k = 0; k < 4; k++)   // 4 x K=16 per 64-half chunk
                        mma_f16_ss(tmem, ad + k * 2, bd + k * 2, IDESC_F16,
                                   !(kt == 0 && k == 0));
                    asm volatile(
                        "tcgen05.commit.cta_group::1.mbarrier::arrive::one.shared::cluster.b64 [%0];"
                        :: "r"(MBAR(st)) : "memory");
                }
            }

            if (kt >= 1) {
                const int ws = (kt - 1) % STAGES;
                if (ws == 0)      { MBARRIER_WAIT_PARITY(MBAR(0), ph0); ph0 ^= 1; }
                else if (ws == 1) { MBARRIER_WAIT_PARITY(MBAR(1), ph1); ph1 ^= 1; }
                else              { MBARRIER_WAIT_PARITY(MBAR(2), ph2); ph2 ^= 1; }
            }
            if (kt + 2 < NKCH)
                load_stage(smem_base, (kt + 2) % STAGES, kt + 2, m0, n0, tid);
        }

        {
            const int ws = (NKCH - 1) % STAGES;
            if (ws == 0)      { MBARRIER_WAIT_PARITY(MBAR(0), ph0); ph0 ^= 1; }
            else if (ws == 1) { MBARRIER_WAIT_PARITY(MBAR(1), ph1); ph1 ^= 1; }
            else              { MBARRIER_WAIT_PARITY(MBAR(2), ph2); ph2 ^= 1; }
        }
        asm volatile("tcgen05.fence::after_thread_sync;" ::: "memory");

        const int m = m0 + wid * 32 + lid;
        float* gout = g_G + (size_t)m * NCOLS + n0;
#pragma unroll
        for (int c0 = 0; c0 < GBN; c0 += 32) {
            uint32_t d[32];
            TCGEN05_LD_32X32B_X32(d, tmem + c0);
            asm volatile("tcgen05.wait::ld.sync.aligned;" ::: "memory");
#pragma unroll
            for (int c = 0; c < 32; c += 4) {
                *(float4*)(gout + c0 + c) = make_float4(
                    __uint_as_float(d[c]),     __uint_as_float(d[c + 1]),
                    __uint_as_float(d[c + 2]), __uint_as_float(d[c + 3]));
            }
        }
        asm volatile("tcgen05.fence::before_thread_sync;" ::: "memory");
        __syncthreads();
    }

    __syncthreads();
    if (wid == 0)
        asm volatile("tcgen05.dealloc.cta_group::1.sync.aligned.b32 %0, %1;" :: "r"(tmem), "r"(128u));
#endif  // HAS_TCGEN05
}

// ===========================================================================
// GEMM path B (fallback, baseline ISA): fp16 mma.sync.m16n8k16
//   128x128x32 block tile, 8 warps (4x2), warp tile 32x64, reg double-buffer
// ===========================================================================
#define BM 128
#define BN 128
#define BK 32
#define HPAD 40   // 32 + 8 halves padding

__global__ __launch_bounds__(256) void gemm_fp16_kernel()
{
    __shared__ __half sA[BM][HPAD];
    __shared__ __half sB[BN][HPAD];

    const int tid  = threadIdx.x;
    const int n0   = blockIdx.x * BN;
    const int m0   = blockIdx.y * BM;

    const __half* Asrc = g_Xh + (size_t)m0 * KDIM;
    const __half* Bsrc = g_Wh + (size_t)n0 * KDIM;

    const int warp = tid >> 5;
    const int lane = tid & 31;
    const int wm   = warp >> 1;     // 0..3
    const int wn   = warp & 1;      // 0..1
    const int lr   = lane >> 2;     // 0..7
    const int lc   = lane & 3;      // 0..3

    float4 ra[2], rb[2];

    // prologue: k-tile 0
#pragma unroll
    for (int i = 0; i < 2; i++) {
        int slot = tid + i * 256;         // 0..511
        int row  = slot >> 2;             // 0..127
        int c8   = slot & 3;              // 8-half chunk
        ra[i] = *(const float4*)(Asrc + (size_t)row * KDIM + c8 * 8);
        rb[i] = *(const float4*)(Bsrc + (size_t)row * KDIM + c8 * 8);
    }
#pragma unroll
    for (int i = 0; i < 2; i++) {
        int slot = tid + i * 256;
        int row  = slot >> 2;
        int c8   = slot & 3;
        *(float4*)&sA[row][c8 * 8] = ra[i];
        *(float4*)&sB[row][c8 * 8] = rb[i];
    }
    __syncthreads();

    float acc[2][8][4];
#pragma unroll
    for (int mt = 0; mt < 2; mt++)
#pragma unroll
        for (int nt = 0; nt < 8; nt++)
#pragma unroll
            for (int r = 0; r < 4; r++) acc[mt][nt][r] = 0.0f;

    const int NK = KDIM / BK;  // 16
    for (int kt = 0; kt < NK; kt++) {
        if (kt < NK - 1) {
#pragma unroll
            for (int i = 0; i < 2; i++) {
                int slot = tid + i * 256;
                int row  = slot >> 2;
                int c8   = slot & 3;
                ra[i] = *(const float4*)(Asrc + (size_t)row * KDIM + (kt + 1) * BK + c8 * 8);
                rb[i] = *(const float4*)(Bsrc + (size_t)row * KDIM + (kt + 1) * BK + c8 * 8);
            }
        }

#pragma unroll
        for (int ks = 0; ks < 2; ks++) {          // 2 x k16 per BK=32
            const int kc = ks * 16 + lc * 2;
            uint32_t afr[2][4];
            uint32_t bfr[8][2];
#pragma unroll
            for (int mt = 0; mt < 2; mt++) {
                int r = wm * 32 + mt * 16 + lr;
                afr[mt][0] = *(const uint32_t*)&sA[r    ][kc    ];
                afr[mt][1] = *(const uint32_t*)&sA[r + 8][kc    ];
                afr[mt][2] = *(const uint32_t*)&sA[r    ][kc + 8];
                afr[mt][3] = *(const uint32_t*)&sA[r + 8][kc + 8];
            }
#pragma unroll
            for (int nt = 0; nt < 8; nt++) {
                int nr = wn * 64 + nt * 8 + lr;
                bfr[nt][0] = *(const uint32_t*)&sB[nr][kc    ];
                bfr[nt][1] = *(const uint32_t*)&sB[nr][kc + 8];
            }
#pragma unroll
            for (int mt = 0; mt < 2; mt++)
#pragma unroll
                for (int nt = 0; nt < 8; nt++)
                    asm volatile(
                        "mma.sync.aligned.m16n8k16.row.col.f32.f16.f16.f32 "
                        "{%0,%1,%2,%3}, {%4,%5,%6,%7}, {%8,%9}, {%0,%1,%2,%3};"
                        : "+f"(acc[mt][nt][0]), "+f"(acc[mt][nt][1]),
                          "+f"(acc[mt][nt][2]), "+f"(acc[mt][nt][3])
                        : "r"(afr[mt][0]), "r"(afr[mt][1]), "r"(afr[mt][2]), "r"(afr[mt][3]),
                          "r"(bfr[nt][0]), "r"(bfr[nt][1]));
        }

        __syncthreads();
        if (kt < NK - 1) {
#pragma unroll
            for (int i = 0; i < 2; i++) {
                int slot = tid + i * 256;
                int row  = slot >> 2;
                int c8   = slot & 3;
                *(float4*)&sA[row][c8 * 8] = ra[i];
                *(float4*)&sB[row][c8 * 8] = rb[i];
            }
            __syncthreads();
        }
    }

#pragma unroll
    for (int mt = 0; mt < 2; mt++) {
#pragma unroll
        for (int nt = 0; nt < 8; nt++) {
            int r0  = m0 + wm * 32 + mt * 16 + lr;
            int col = n0 + wn * 64 + nt * 8 + lc * 2;
            *(float2*)(g_G + (size_t)r0 * NCOLS + col)       = make_float2(acc[mt][nt][0], acc[mt][nt][1]);
            *(float2*)(g_G + (size_t)(r0 + 8) * NCOLS + col) = make_float2(acc[mt][nt][2], acc[mt][nt][3]);
        }
    }
}

// ===========================================================================
// Chunked scan: 3 passes.
//   lane = dir*8192 + b*512 + h  (16384 lanes); chunk c covers 256 seq steps.
//   Pass1: per-(lane,chunk) A=prod(1-f), C=local h (h_in=0). 131072 threads.
//   Pass2: per-lane serial combine over 8 chunks -> Hin per chunk.
//   Pass3: re-scan with h0=Hin, y = o*h. 131072 threads.
// ===========================================================================
#define SCH 8   // inner prefetch chunk

__global__ __launch_bounds__(256) void scan_phase1(
    const float* __restrict__ bfw,
    const float* __restrict__ bbw)
{
    const int t   = blockIdx.x * 256 + threadIdx.x;   // 0..131071
    const int h   = t & 511;
    const int c   = (t >> 9) & 7;
    const int bi  = (t >> 12) & 15;
    const int dir = t >> 16;
    const int lane = dir * 8192 + bi * 512 + h;

    const float* bias = dir ? bbw : bfw;
    const float bz = bias[h];
    const float bf = bias[HID + h];

    // seq position u in [c*256, c*256+256); row s = u (fw) or SEQ-1-u (bw)
    const int s0 = dir ? (SEQ - 1 - c * CHLEN) : (c * CHLEN);
    const long long step = dir ? -(long long)(BATCH * NCOLS) : (long long)(BATCH * NCOLS);
    const float* gp = g_G + ((long long)(s0 * BATCH + bi)) * NCOLS + dir * 3 * HID + h;

    float zc[SCH], fc[SCH];
#pragma unroll
    for (int j = 0; j < SCH; j++) { zc[j] = gp[0]; fc[j] = gp[HID]; gp += step; }

    float hs = 0.0f, A = 1.0f;
    const int NIT = CHLEN / SCH;  // 32
    for (int it = 0; it < NIT; it++) {
        float zn[SCH], fn[SCH];
        if (it < NIT - 1) {
#pragma unroll
            for (int j = 0; j < SCH; j++) { zn[j] = gp[0]; fn[j] = gp[HID]; gp += step; }
        }
#pragma unroll
        for (int j = 0; j < SCH; j++) {
            float z = tanh_(zc[j] + bz);
            float f = sigm_(fc[j] + bf);
            hs = fmaf(f, z - hs, hs);
            A *= (1.0f - f);
        }
#pragma unroll
        for (int j = 0; j < SCH; j++) { zc[j] = zn[j]; fc[j] = fn[j]; }
    }

    g_A[c * NLANE + lane] = A;
    g_C[c * NLANE + lane] = hs;
}

__global__ __launch_bounds__(256) void scan_combine()
{
    const int lane = blockIdx.x * 256 + threadIdx.x;  // 0..16383
    float H = 0.0f;
#pragma unroll
    for (int c = 0; c < NCHK; c++) {
        g_Hin[c * NLANE + lane] = H;
        H = g_A[c * NLANE + lane] * H + g_C[c * NLANE + lane];
    }
}

__global__ __launch_bounds__(256) void scan_phase3(
    const float* __restrict__ bfw,
    const float* __restrict__ bbw,
    float* __restrict__ Y)
{
    const int t   = blockIdx.x * 256 + threadIdx.x;   // 0..131071
    const int h   = t & 511;
    const int c   = (t >> 9) & 7;
    const int bi  = (t >> 12) & 15;
    const int dir = t >> 16;
    const int lane = dir * 8192 + bi * 512 + h;

    const float* bias = dir ? bbw : bfw;
    const float bz = bias[h];
    const float bf = bias[HID + h];
    const float bo = bias[2 * HID + h];

    const int s0 = dir ? (SEQ - 1 - c * CHLEN) : (c * CHLEN);
    const long long step  = dir ? -(long long)(BATCH * NCOLS)   : (long long)(BATCH * NCOLS);
    const long long ystep = dir ? -(long long)(BATCH * 2 * HID) : (long long)(BATCH * 2 * HID);
    const float* gp = g_G + ((long long)(s0 * BATCH + bi)) * NCOLS + dir * 3 * HID + h;
    float*       yp = Y   + ((long long)(s0 * BATCH + bi)) * (2 * HID) + dir * HID + h;

    float zc[SCH], fc[SCH], oc[SCH];
#pragma unroll
    for (int j = 0; j < SCH; j++) {
        zc[j] = gp[0]; fc[j] = gp[HID]; oc[j] = gp[2 * HID]; gp += step;
    }

    float hs = g_Hin[c * NLANE + lane];
    const int NIT = CHLEN / SCH;  // 32
    for (int it = 0; it < NIT; it++) {
        float zn[SCH], fn[SCH], on[SCH];
        if (it < NIT - 1) {
#pragma unroll
            for (int j = 0; j < SCH; j++) {
                zn[j] = gp[0]; fn[j] = gp[HID]; on[j] = gp[2 * HID]; gp += step;
            }
        }
#pragma unroll
        for (int j = 0; j < SCH; j++) {
            float z = tanh_(zc[j] + bz);
            float f = sigm_(fc[j] + bf);
            float o = sigm_(oc[j] + bo);
            hs = fmaf(f, z - hs, hs);
            yp[0] = o * hs;
            yp += ystep;
        }
#pragma unroll
        for (int j = 0; j < SCH; j++) { zc[j] = zn[j]; fc[j] = fn[j]; oc[j] = on[j]; }
    }
}

// ---------------------------------------------------------------------------
// Launch
// ---------------------------------------------------------------------------
extern "C" void kernel_launch(void* const* d_in, const int* in_sizes, int n_in,
                              void* d_out, int out_size)
{
    const float* X   = (const float*)d_in[0];
    const float* Wfw = (const float*)d_in[1];
    const float* bfw = (const float*)d_in[2];
    const float* Wbw = (const float*)d_in[3];
    const float* bbw = (const float*)d_in[4];
    float* Y = (float*)d_out;

    // Which device-code pass is loaded? (host-side query; capture-safe)
    cudaFuncAttributes pa;
    bool use_tc = false;
    if (cudaFuncGetAttributes(&pa, probe_kernel) == cudaSuccess)
        use_tc = (pa.sharedSizeBytes >= 4096);

    cvt_kernel<<<17920, 256>>>(X, Wfw, Wbw);

    if (use_tc) {
        cudaFuncSetAttribute(gemm_tc_kernel, cudaFuncAttributeMaxDynamicSharedMemorySize, GEMM_SMEM);
        gemm_tc_kernel<<<GEMM_CTAS, 128, GEMM_SMEM>>>();
    } else {
        dim3 ggrid(NCOLS / BN, MROWS / BM);   // (24, 256)
        gemm_fp16_kernel<<<ggrid, 256>>>();
    }

    scan_phase1<<<131072 / 256, 256>>>(bfw, bbw);
    scan_combine<<<16384 / 256, 256>>>();
    scan_phase3<<<131072 / 256, 256>>>(bfw, bbw, Y);
}

// round 7
// speedup vs baseline: 4.8085x; 1.3465x over previous
#include <cuda_runtime.h>
#include <cuda_fp16.h>
#include <cuda_bf16.h>
#include <cstdint>

// ---------------------------------------------------------------------------
// Problem constants
// ---------------------------------------------------------------------------
#define SEQ   2048
#define BATCH 16
#define DIN   512
#define HID   512
#define MROWS (SEQ*BATCH)       // 32768
#define NCOLS (3*HID*2)         // 3072
#define KDIM  DIN               // 512

// Feature gate: tcgen05 only exists in an arch-specific (sm_103a/sm_100a) pass.
#if defined(__CUDA_ARCH__) && (defined(__CUDA_ARCH_FEAT_SM103_ALL) || defined(__CUDA_ARCH_FEAT_SM100_ALL))
#define HAS_TCGEN05 1
#else
#define HAS_TCGEN05 0
#endif

// Scratch (static device arrays; no allocation allowed)
__device__ __half g_G[(size_t)MROWS * NCOLS];   // pre-activation gates (fp16)
__device__ __half g_Xh[(size_t)MROWS * KDIM];   // X in fp16
__device__ __half g_Wh[(size_t)NCOLS * KDIM];   // [W_fw; W_bw] in fp16

// Chunked-scan aggregates: 16384 lanes x 8 chunks, layout [chunk][lane]
#define NLANE 16384
#define NCHK  8
#define CHLEN (SEQ / NCHK)      // 256
__device__ float g_A[NCHK * NLANE];
__device__ float g_C[NCHK * NLANE];
__device__ float g_Hin[NCHK * NLANE];

// ---------------------------------------------------------------------------
// Probe kernel: static smem size tells the host whether the loaded device
// code came from the arch-specific (tcgen05-capable) pass.
// ---------------------------------------------------------------------------
__global__ void probe_kernel(float* p) {
#if HAS_TCGEN05
    __shared__ volatile float s[2048];
#else
    __shared__ volatile float s[64];
#endif
    s[threadIdx.x & 63] = p[0];
    p[1] = s[(threadIdx.x + 1) & 63];
}

// ---------------------------------------------------------------------------
// Common helpers
// ---------------------------------------------------------------------------
__device__ __forceinline__ uint32_t smem_to_u32(const void* p) {
    uint32_t a;
    asm("{ .reg .u64 t; cvta.to.shared.u64 t, %1; cvt.u32.u64 %0, t; }" : "=r"(a) : "l"(p));
    return a;
}

__device__ __forceinline__ float ex2f(float x) {
    float y; asm("ex2.approx.ftz.f32 %0, %1;" : "=f"(y) : "f"(x)); return y;
}
__device__ __forceinline__ float rcpf(float x) {
    float y; asm("rcp.approx.ftz.f32 %0, %1;" : "=f"(y) : "f"(x)); return y;
}
__device__ __forceinline__ float sigm_(float x) {
    return rcpf(1.0f + ex2f(-1.4426950408889634f * x));
}
__device__ __forceinline__ float tanh_(float x) {
    return fmaf(2.0f, rcpf(1.0f + ex2f(-2.8853900817779268f * x)), -1.0f);
}

// ---------------------------------------------------------------------------
// Kernel 0: fp32 -> fp16 conversion (X, W_fw, W_bw)
// ---------------------------------------------------------------------------
__global__ __launch_bounds__(256) void cvt_kernel(
    const float* __restrict__ X,
    const float* __restrict__ Wfw,
    const float* __restrict__ Wbw)
{
    const long long NX = (long long)MROWS * KDIM;     // 16777216
    const long long NW = (long long)(3 * HID) * KDIM; // 786432 per direction
    long long i = ((long long)blockIdx.x * blockDim.x + threadIdx.x) * 4;

    const float* src;
    __half* dst;
    if (i < NX)           { src = X   + i;             dst = g_Xh + i; }
    else if (i < NX + NW) { src = Wfw + (i - NX);      dst = g_Wh + (i - NX); }
    else                  { src = Wbw + (i - NX - NW); dst = g_Wh + (i - NX); }

    float4 v = *(const float4*)src;
    *(__half2*)dst       = __floats2half2_rn(v.x, v.y);
    *(__half2*)(dst + 2) = __floats2half2_rn(v.z, v.w);
}

// ===========================================================================
// GEMM path A: tcgen05 (only present in arch-specific pass)
// ===========================================================================
#define GBM 128
#define GBN 128
#define GBK 64
#define NKCH (KDIM / GBK)        // 8
#define STAGES 3
#define STAGE_BYTES (GBM * 128)  // 16384 per operand per stage
#define SMEM_A_OFF 1024
#define SMEM_B_OFF (1024 + STAGES * STAGE_BYTES)
#define GEMM_SMEM  (1024 + 2 * STAGES * STAGE_BYTES)   // 99328
#define N_MTILE (MROWS / GBM)    // 256
#define N_NTILE (NCOLS / GBN)    // 24
#define N_TILES (N_MTILE * N_NTILE)  // 6144
#define GEMM_CTAS 296

#if HAS_TCGEN05
#define SMEM_SWIZZLE_128B(o) ((o) ^ (((o) >> 3) & 0x70))

static constexpr uint64_t SMEM_DESC_BASE_SW128 =
    (uint64_t(2) << 61) | (uint64_t(1) << 46) | (uint64_t(64) << 32) | (uint64_t(1) << 16);
#define MAKE_SMEM_DESC(base_addr) \
    (SMEM_DESC_BASE_SW128 | ((uint64_t)((base_addr) >> 4) & 0x3FFF))

#define MBARRIER_INIT(addr, cnt) \
    asm volatile("mbarrier.init.shared.b64 [%0], %1;" :: "r"((uint32_t)(addr)), "r"((uint32_t)(cnt)) : "memory")

#define MBARRIER_WAIT_PARITY(mbar_smem_addr, phase_parity) do { \
    uint32_t _mbar = (uint32_t)(mbar_smem_addr); \
    uint32_t _parity = (uint32_t)(phase_parity); \
    uint32_t _done; \
    asm volatile( \
        "{\n\t.reg .pred p;\n\t" \
        "mbarrier.try_wait.parity.acquire.cta.shared::cta.b64 p, [%1], %2;\n\t" \
        "selp.b32 %0, 1, 0, p;\n\t}" \
        : "=r"(_done) : "r"(_mbar), "r"(_parity) : "memory"); \
    if (!_done) { \
        asm volatile( \
            "{\n\t.reg .pred P1;\n\t" \
            "WAIT_LOOP_%=:\n\t" \
            "mbarrier.try_wait.parity.acquire.cta.shared::cta.b64 P1, [%0], %1, 0x989680;\n\t" \
            "@P1 bra.uni WAIT_DONE_%=;\n\t" \
            "bra.uni WAIT_LOOP_%=;\n\t" \
            "WAIT_DONE_%=:\n\t}" \
            :: "r"(_mbar), "r"(_parity) : "memory"); \
    } \
} while(0)

__device__ __forceinline__ uint32_t elect_one_pred() {
    uint32_t pred;
    asm volatile(
        "{\n\t.reg .pred p;\n\t"
        "elect.sync _|p, 0xFFFFFFFF;\n\t"
        "selp.b32 %0, 1, 0, p;\n\t}"
        : "=r"(pred));
    return pred;
}

#define TCGEN05_LD_32X32B_X32(r, tmem_addr) \
    asm volatile( \
        "tcgen05.ld.sync.aligned.32x32b.x32.b32 " \
        "{%0, %1, %2, %3, %4, %5, %6, %7, " \
        " %8, %9, %10, %11, %12, %13, %14, %15, " \
        " %16, %17, %18, %19, %20, %21, %22, %23, " \
        " %24, %25, %26, %27, %28, %29, %30, %31}, [%32];" \
        : "=r"((r)[0]),  "=r"((r)[1]),  "=r"((r)[2]),  "=r"((r)[3]), \
          "=r"((r)[4]),  "=r"((r)[5]),  "=r"((r)[6]),  "=r"((r)[7]), \
          "=r"((r)[8]),  "=r"((r)[9]),  "=r"((r)[10]), "=r"((r)[11]), \
          "=r"((r)[12]), "=r"((r)[13]), "=r"((r)[14]), "=r"((r)[15]), \
          "=r"((r)[16]), "=r"((r)[17]), "=r"((r)[18]), "=r"((r)[19]), \
          "=r"((r)[20]), "=r"((r)[21]), "=r"((r)[22]), "=r"((r)[23]), \
          "=r"((r)[24]), "=r"((r)[25]), "=r"((r)[26]), "=r"((r)[27]), \
          "=r"((r)[28]), "=r"((r)[29]), "=r"((r)[30]), "=r"((r)[31]) \
        : "r"(tmem_addr))

// idesc: dtype=F32 (1<<4), atype=btype=F16 (0), N/8<<17, M/16<<24
#define IDESC_F16 ((1u << 4) | ((GBN / 8u) << 17) | ((GBM / 16u) << 24))

__device__ __forceinline__ void mma_f16_ss(uint32_t d_tmem, uint64_t a_desc, uint64_t b_desc,
                                           uint32_t idesc, bool accum) {
    uint32_t en = accum ? 1u : 0u;
    asm volatile(
        "{\n\t.reg .pred p;\n\t"
        "setp.ne.u32 p, %4, 0;\n\t"
        "tcgen05.mma.cta_group::1.kind::f16 [%0], %1, %2, %3, {%5, %5, %5, %5}, p;\n\t}"
        :: "r"(d_tmem), "l"(a_desc), "l"(b_desc), "r"(idesc), "r"(en), "r"(0u)
        : "memory");
}

__device__ __forceinline__ void cp_async16(uint32_t dst, const void* src) {
    asm volatile("cp.async.cg.shared.global [%0], [%1], 16;" :: "r"(dst), "l"(src) : "memory");
}
__device__ __forceinline__ void cp_commit() {
    asm volatile("cp.async.commit_group;" ::: "memory");
}
template<int N> __device__ __forceinline__ void cp_wait() {
    asm volatile("cp.async.wait_group %0;" :: "n"(N) : "memory");
}

__device__ __forceinline__ void load_stage(uint32_t smem_base, int st, int kt,
                                           int m0, int n0, int tid)
{
    const __half* Asrc = g_Xh + (size_t)m0 * KDIM + kt * GBK;
    const __half* Bsrc = g_Wh + (size_t)n0 * KDIM + kt * GBK;
    uint32_t abase = smem_base + SMEM_A_OFF + st * STAGE_BYTES;
    uint32_t bbase = smem_base + SMEM_B_OFF + st * STAGE_BYTES;
#pragma unroll
    for (int i = 0; i < 8; i++) {
        int chunk = i * 128 + tid;        // 0..1023
        int row   = chunk >> 3;           // 0..127
        int c16   = chunk & 7;            // 16B column chunk
        uint32_t off = SMEM_SWIZZLE_128B((uint32_t)(row * 128 + c16 * 16));
        cp_async16(abase + off, Asrc + (size_t)row * KDIM + c16 * 8);
        cp_async16(bbase + off, Bsrc + (size_t)row * KDIM + c16 * 8);
    }
    cp_commit();
}
#endif  // HAS_TCGEN05

#define MBAR(s) (smem_base + 16 + (s) * 8)

__global__ void __launch_bounds__(128, 2) __cluster_dims__(1, 1, 1) gemm_tc_kernel()
{
#if HAS_TCGEN05
    extern __shared__ char smem[];
    uint32_t smem_base = smem_to_u32(smem);
    const int tid = threadIdx.x;
    const int wid = tid >> 5;
    const int lid = tid & 31;

    if (tid < STAGES) MBARRIER_INIT(MBAR(tid), 1);
    if (wid == 0) {
        asm volatile("tcgen05.alloc.cta_group::1.sync.aligned.shared::cta.b32 [%0], %1;"
            :: "r"(smem_base), "r"(128u) : "memory");
        asm volatile("tcgen05.relinquish_alloc_permit.cta_group::1.sync.aligned;");
    }
    __syncthreads();

    uint32_t tmem;
    asm volatile("ld.shared.b32 %0, [%1];" : "=r"(tmem) : "r"(smem_base));

    int ph0 = 0, ph1 = 0, ph2 = 0;

    for (int tile = blockIdx.x; tile < N_TILES; tile += GEMM_CTAS) {
        const int m0 = (tile / N_NTILE) * GBM;
        const int n0 = (tile % N_NTILE) * GBN;

        load_stage(smem_base, 0, 0, m0, n0, tid);
        load_stage(smem_base, 1, 1, m0, n0, tid);

#pragma unroll
        for (int kt = 0; kt < NKCH; kt++) {
            const int st = kt % STAGES;
            if (kt == NKCH - 1) cp_wait<0>(); else cp_wait<1>();
            __syncthreads();
            asm volatile("fence.proxy.async.shared::cta;" ::: "memory");

            if (wid == 0) {
                if (elect_one_pred()) {
                    uint64_t ad = MAKE_SMEM_DESC(smem_base + SMEM_A_OFF + st * STAGE_BYTES);
                    uint64_t bd = MAKE_SMEM_DESC(smem_base + SMEM_B_OFF + st * STAGE_BYTES);
#pragma unroll
                    for (int k = 0; k < 4; k++)   // 4 x K=16 per 64-half chunk
                        mma_f16_ss(tmem, ad + k * 2, bd + k * 2, IDESC_F16,
                                   !(kt == 0 && k == 0));
                    asm volatile(
                        "tcgen05.commit.cta_group::1.mbarrier::arrive::one.shared::cluster.b64 [%0];"
                        :: "r"(MBAR(st)) : "memory");
                }
            }

            if (kt >= 1) {
                const int ws = (kt - 1) % STAGES;
                if (ws == 0)      { MBARRIER_WAIT_PARITY(MBAR(0), ph0); ph0 ^= 1; }
                else if (ws == 1) { MBARRIER_WAIT_PARITY(MBAR(1), ph1); ph1 ^= 1; }
                else              { MBARRIER_WAIT_PARITY(MBAR(2), ph2); ph2 ^= 1; }
            }
            if (kt + 2 < NKCH)
                load_stage(smem_base, (kt + 2) % STAGES, kt + 2, m0, n0, tid);
        }

        {
            const int ws = (NKCH - 1) % STAGES;
            if (ws == 0)      { MBARRIER_WAIT_PARITY(MBAR(0), ph0); ph0 ^= 1; }
            else if (ws == 1) { MBARRIER_WAIT_PARITY(MBAR(1), ph1); ph1 ^= 1; }
            else              { MBARRIER_WAIT_PARITY(MBAR(2), ph2); ph2 ^= 1; }
        }
        asm volatile("tcgen05.fence::after_thread_sync;" ::: "memory");

        // Epilogue: TMEM fp32 -> fp16, 64B (4x int4) per 32-col batch per row.
        const int m = m0 + wid * 32 + lid;
        __half* gout = g_G + (size_t)m * NCOLS + n0;
#pragma unroll
        for (int c0 = 0; c0 < GBN; c0 += 32) {
            uint32_t d[32];
            TCGEN05_LD_32X32B_X32(d, tmem + c0);
            asm volatile("tcgen05.wait::ld.sync.aligned;" ::: "memory");
            uint32_t hp[16];
#pragma unroll
            for (int c = 0; c < 16; c++) {
                __half2 h2 = __floats2half2_rn(__uint_as_float(d[2 * c]),
                                               __uint_as_float(d[2 * c + 1]));
                hp[c] = *(uint32_t*)&h2;
            }
#pragma unroll
            for (int q = 0; q < 4; q++) {
                *(uint4*)(gout + c0 + q * 8) = make_uint4(
                    hp[q * 4], hp[q * 4 + 1], hp[q * 4 + 2], hp[q * 4 + 3]);
            }
        }
        asm volatile("tcgen05.fence::before_thread_sync;" ::: "memory");
        __syncthreads();
    }

    __syncthreads();
    if (wid == 0)
        asm volatile("tcgen05.dealloc.cta_group::1.sync.aligned.b32 %0, %1;" :: "r"(tmem), "r"(128u));
#endif  // HAS_TCGEN05
}

// ===========================================================================
// GEMM path B (fallback, baseline ISA): fp16 mma.sync.m16n8k16
// ===========================================================================
#define BM 128
#define BN 128
#define BK 32
#define HPAD 40   // 32 + 8 halves padding

__global__ __launch_bounds__(256) void gemm_fp16_kernel()
{
    __shared__ __half sA[BM][HPAD];
    __shared__ __half sB[BN][HPAD];

    const int tid  = threadIdx.x;
    const int n0   = blockIdx.x * BN;
    const int m0   = blockIdx.y * BM;

    const __half* Asrc = g_Xh + (size_t)m0 * KDIM;
    const __half* Bsrc = g_Wh + (size_t)n0 * KDIM;

    const int warp = tid >> 5;
    const int lane = tid & 31;
    const int wm   = warp >> 1;     // 0..3
    const int wn   = warp & 1;      // 0..1
    const int lr   = lane >> 2;     // 0..7
    const int lc   = lane & 3;      // 0..3

    float4 ra[2], rb[2];

#pragma unroll
    for (int i = 0; i < 2; i++) {
        int slot = tid + i * 256;
        int row  = slot >> 2;
        int c8   = slot & 3;
        ra[i] = *(const float4*)(Asrc + (size_t)row * KDIM + c8 * 8);
        rb[i] = *(const float4*)(Bsrc + (size_t)row * KDIM + c8 * 8);
    }
#pragma unroll
    for (int i = 0; i < 2; i++) {
        int slot = tid + i * 256;
        int row  = slot >> 2;
        int c8   = slot & 3;
        *(float4*)&sA[row][c8 * 8] = ra[i];
        *(float4*)&sB[row][c8 * 8] = rb[i];
    }
    __syncthreads();

    float acc[2][8][4];
#pragma unroll
    for (int mt = 0; mt < 2; mt++)
#pragma unroll
        for (int nt = 0; nt < 8; nt++)
#pragma unroll
            for (int r = 0; r < 4; r++) acc[mt][nt][r] = 0.0f;

    const int NK = KDIM / BK;  // 16
    for (int kt = 0; kt < NK; kt++) {
        if (kt < NK - 1) {
#pragma unroll
            for (int i = 0; i < 2; i++) {
                int slot = tid + i * 256;
                int row  = slot >> 2;
                int c8   = slot & 3;
                ra[i] = *(const float4*)(Asrc + (size_t)row * KDIM + (kt + 1) * BK + c8 * 8);
                rb[i] = *(const float4*)(Bsrc + (size_t)row * KDIM + (kt + 1) * BK + c8 * 8);
            }
        }

#pragma unroll
        for (int ks = 0; ks < 2; ks++) {
            const int kc = ks * 16 + lc * 2;
            uint32_t afr[2][4];
            uint32_t bfr[8][2];
#pragma unroll
            for (int mt = 0; mt < 2; mt++) {
                int r = wm * 32 + mt * 16 + lr;
                afr[mt][0] = *(const uint32_t*)&sA[r    ][kc    ];
                afr[mt][1] = *(const uint32_t*)&sA[r + 8][kc    ];
                afr[mt][2] = *(const uint32_t*)&sA[r    ][kc + 8];
                afr[mt][3] = *(const uint32_t*)&sA[r + 8][kc + 8];
            }
#pragma unroll
            for (int nt = 0; nt < 8; nt++) {
                int nr = wn * 64 + nt * 8 + lr;
                bfr[nt][0] = *(const uint32_t*)&sB[nr][kc    ];
                bfr[nt][1] = *(const uint32_t*)&sB[nr][kc + 8];
            }
#pragma unroll
            for (int mt = 0; mt < 2; mt++)
#pragma unroll
                for (int nt = 0; nt < 8; nt++)
                    asm volatile(
                        "mma.sync.aligned.m16n8k16.row.col.f32.f16.f16.f32 "
                        "{%0,%1,%2,%3}, {%4,%5,%6,%7}, {%8,%9}, {%0,%1,%2,%3};"
                        : "+f"(acc[mt][nt][0]), "+f"(acc[mt][nt][1]),
                          "+f"(acc[mt][nt][2]), "+f"(acc[mt][nt][3])
                        : "r"(afr[mt][0]), "r"(afr[mt][1]), "r"(afr[mt][2]), "r"(afr[mt][3]),
                          "r"(bfr[nt][0]), "r"(bfr[nt][1]));
        }

        __syncthreads();
        if (kt < NK - 1) {
#pragma unroll
            for (int i = 0; i < 2; i++) {
                int slot = tid + i * 256;
                int row  = slot >> 2;
                int c8   = slot & 3;
                *(float4*)&sA[row][c8 * 8] = ra[i];
                *(float4*)&sB[row][c8 * 8] = rb[i];
            }
            __syncthreads();
        }
    }

#pragma unroll
    for (int mt = 0; mt < 2; mt++) {
#pragma unroll
        for (int nt = 0; nt < 8; nt++) {
            int r0  = m0 + wm * 32 + mt * 16 + lr;
            int col = n0 + wn * 64 + nt * 8 + lc * 2;
            __half2 h0 = __floats2half2_rn(acc[mt][nt][0], acc[mt][nt][1]);
            __half2 h1 = __floats2half2_rn(acc[mt][nt][2], acc[mt][nt][3]);
            *(__half2*)(g_G + (size_t)r0 * NCOLS + col)       = h0;
            *(__half2*)(g_G + (size_t)(r0 + 8) * NCOLS + col) = h1;
        }
    }
}

// ===========================================================================
// Chunked scan: 3 passes (fp16 gate reads).
// ===========================================================================
#define SCH 8   // inner prefetch chunk

__global__ __launch_bounds__(256) void scan_phase1(
    const float* __restrict__ bfw,
    const float* __restrict__ bbw)
{
    const int t   = blockIdx.x * 256 + threadIdx.x;   // 0..131071
    const int h   = t & 511;
    const int c   = (t >> 9) & 7;
    const int bi  = (t >> 12) & 15;
    const int dir = t >> 16;
    const int lane = dir * 8192 + bi * 512 + h;

    const float* bias = dir ? bbw : bfw;
    const float bz = bias[h];
    const float bf = bias[HID + h];

    const int s0 = dir ? (SEQ - 1 - c * CHLEN) : (c * CHLEN);
    const long long step = dir ? -(long long)(BATCH * NCOLS) : (long long)(BATCH * NCOLS);
    const __half* gp = g_G + ((long long)(s0 * BATCH + bi)) * NCOLS + dir * 3 * HID + h;

    float zc[SCH], fc[SCH];
#pragma unroll
    for (int j = 0; j < SCH; j++) {
        zc[j] = __half2float(gp[0]);
        fc[j] = __half2float(gp[HID]);
        gp += step;
    }

    float hs = 0.0f, A = 1.0f;
    const int NIT = CHLEN / SCH;  // 32
    for (int it = 0; it < NIT; it++) {
        float zn[SCH], fn[SCH];
        if (it < NIT - 1) {
#pragma unroll
            for (int j = 0; j < SCH; j++) {
                zn[j] = __half2float(gp[0]);
                fn[j] = __half2float(gp[HID]);
                gp += step;
            }
        }
#pragma unroll
        for (int j = 0; j < SCH; j++) {
            float z = tanh_(zc[j] + bz);
            float f = sigm_(fc[j] + bf);
            hs = fmaf(f, z - hs, hs);
            A *= (1.0f - f);
        }
#pragma unroll
        for (int j = 0; j < SCH; j++) { zc[j] = zn[j]; fc[j] = fn[j]; }
    }

    g_A[c * NLANE + lane] = A;
    g_C[c * NLANE + lane] = hs;
}

__global__ __launch_bounds__(256) void scan_combine()
{
    const int lane = blockIdx.x * 256 + threadIdx.x;  // 0..16383
    float H = 0.0f;
#pragma unroll
    for (int c = 0; c < NCHK; c++) {
        g_Hin[c * NLANE + lane] = H;
        H = g_A[c * NLANE + lane] * H + g_C[c * NLANE + lane];
    }
}

__global__ __launch_bounds__(256) void scan_phase3(
    const float* __restrict__ bfw,
    const float* __restrict__ bbw,
    float* __restrict__ Y)
{
    const int t   = blockIdx.x * 256 + threadIdx.x;   // 0..131071
    const int h   = t & 511;
    const int c   = (t >> 9) & 7;
    const int bi  = (t >> 12) & 15;
    const int dir = t >> 16;
    const int lane = dir * 8192 + bi * 512 + h;

    const float* bias = dir ? bbw : bfw;
    const float bz = bias[h];
    const float bf = bias[HID + h];
    const float bo = bias[2 * HID + h];

    const int s0 = dir ? (SEQ - 1 - c * CHLEN) : (c * CHLEN);
    const long long step  = dir ? -(long long)(BATCH * NCOLS)   : (long long)(BATCH * NCOLS);
    const long long ystep = dir ? -(long long)(BATCH * 2 * HID) : (long long)(BATCH * 2 * HID);
    const __half* gp = g_G + ((long long)(s0 * BATCH + bi)) * NCOLS + dir * 3 * HID + h;
    float*        yp = Y   + ((long long)(s0 * BATCH + bi)) * (2 * HID) + dir * HID + h;

    float zc[SCH], fc[SCH], oc[SCH];
#pragma unroll
    for (int j = 0; j < SCH; j++) {
        zc[j] = __half2float(gp[0]);
        fc[j] = __half2float(gp[HID]);
        oc[j] = __half2float(gp[2 * HID]);
        gp += step;
    }

    float hs = g_Hin[c * NLANE + lane];
    const int NIT = CHLEN / SCH;  // 32
    for (int it = 0; it < NIT; it++) {
        float zn[SCH], fn[SCH], on[SCH];
        if (it < NIT - 1) {
#pragma unroll
            for (int j = 0; j < SCH; j++) {
                zn[j] = __half2float(gp[0]);
                fn[j] = __half2float(gp[HID]);
                on[j] = __half2float(gp[2 * HID]);
                gp += step;
            }
        }
#pragma unroll
        for (int j = 0; j < SCH; j++) {
            float z = tanh_(zc[j] + bz);
            float f = sigm_(fc[j] + bf);
            float o = sigm_(oc[j] + bo);
            hs = fmaf(f, z - hs, hs);
            yp[0] = o * hs;
            yp += ystep;
        }
#pragma unroll
        for (int j = 0; j < SCH; j++) { zc[j] = zn[j]; fc[j] = fn[j]; oc[j] = on[j]; }
    }
}

// ---------------------------------------------------------------------------
// Launch
// ---------------------------------------------------------------------------
extern "C" void kernel_launch(void* const* d_in, const int* in_sizes, int n_in,
                              void* d_out, int out_size)
{
    const float* X   = (const float*)d_in[0];
    const float* Wfw = (const float*)d_in[1];
    const float* bfw = (const float*)d_in[2];
    const float* Wbw = (const float*)d_in[3];
    const float* bbw = (const float*)d_in[4];
    float* Y = (float*)d_out;

    cudaFuncAttributes pa;
    bool use_tc = false;
    if (cudaFuncGetAttributes(&pa, probe_kernel) == cudaSuccess)
        use_tc = (pa.sharedSizeBytes >= 4096);

    cvt_kernel<<<17920, 256>>>(X, Wfw, Wbw);

    if (use_tc) {
        cudaFuncSetAttribute(gemm_tc_kernel, cudaFuncAttributeMaxDynamicSharedMemorySize, GEMM_SMEM);
        gemm_tc_kernel<<<GEMM_CTAS, 128, GEMM_SMEM>>>();
    } else {
        dim3 ggrid(NCOLS / BN, MROWS / BM);   // (24, 256)
        gemm_fp16_kernel<<<ggrid, 256>>>();
    }

    scan_phase1<<<131072 / 256, 256>>>(bfw, bbw);
    scan_combine<<<16384 / 256, 256>>>();
    scan_phase3<<<131072 / 256, 256>>>(bfw, bbw, Y);
}

// round 8
// speedup vs baseline: 4.8304x; 1.0046x over previous
#include <cuda_runtime.h>
#include <cuda_fp16.h>
#include <cuda_bf16.h>
#include <cstdint>

// ---------------------------------------------------------------------------
// Problem constants
// ---------------------------------------------------------------------------
#define SEQ   2048
#define BATCH 16
#define DIN   512
#define HID   512
#define MROWS (SEQ*BATCH)       // 32768
#define NCOLS (3*HID*2)         // 3072
#define KDIM  DIN               // 512

// Feature gate: tcgen05 only exists in an arch-specific (sm_103a/sm_100a) pass.
#if defined(__CUDA_ARCH__) && (defined(__CUDA_ARCH_FEAT_SM103_ALL) || defined(__CUDA_ARCH_FEAT_SM100_ALL))
#define HAS_TCGEN05 1
#else
#define HAS_TCGEN05 0
#endif

// Scratch (static device arrays; no allocation allowed)
__device__ __half g_G[(size_t)MROWS * NCOLS];   // pre-activation gates (fp16)
__device__ __half g_Xh[(size_t)MROWS * KDIM];   // X in fp16
__device__ __half g_Wh[(size_t)NCOLS * KDIM];   // [W_fw; W_bw] in fp16

// Chunked-scan aggregates: 16384 lanes x 8 chunks, layout [chunk][lane]
#define NLANE 16384
#define NCHK  8
#define CHLEN (SEQ / NCHK)      // 256
__device__ float g_A[NCHK * NLANE];
__device__ float g_C[NCHK * NLANE];
__device__ float g_Hin[NCHK * NLANE];

// ---------------------------------------------------------------------------
// Probe kernel: static smem size tells the host whether the loaded device
// code came from the arch-specific (tcgen05-capable) pass.
// ---------------------------------------------------------------------------
__global__ void probe_kernel(float* p) {
#if HAS_TCGEN05
    __shared__ volatile float s[2048];
#else
    __shared__ volatile float s[64];
#endif
    s[threadIdx.x & 63] = p[0];
    p[1] = s[(threadIdx.x + 1) & 63];
}

// ---------------------------------------------------------------------------
// Common helpers
// ---------------------------------------------------------------------------
__device__ __forceinline__ uint32_t smem_to_u32(const void* p) {
    uint32_t a;
    asm("{ .reg .u64 t; cvta.to.shared.u64 t, %1; cvt.u32.u64 %0, t; }" : "=r"(a) : "l"(p));
    return a;
}

__device__ __forceinline__ float ex2f(float x) {
    float y; asm("ex2.approx.ftz.f32 %0, %1;" : "=f"(y) : "f"(x)); return y;
}
__device__ __forceinline__ float rcpf(float x) {
    float y; asm("rcp.approx.ftz.f32 %0, %1;" : "=f"(y) : "f"(x)); return y;
}
__device__ __forceinline__ float sigm_(float x) {
    return rcpf(1.0f + ex2f(-1.4426950408889634f * x));
}
__device__ __forceinline__ float tanh_(float x) {
    return fmaf(2.0f, rcpf(1.0f + ex2f(-2.8853900817779268f * x)), -1.0f);
}

// ---------------------------------------------------------------------------
// Kernel 0: fp32 -> fp16 conversion (X, W_fw, W_bw)
// ---------------------------------------------------------------------------
__global__ __launch_bounds__(256) void cvt_kernel(
    const float* __restrict__ X,
    const float* __restrict__ Wfw,
    const float* __restrict__ Wbw)
{
    const long long NX = (long long)MROWS * KDIM;     // 16777216
    const long long NW = (long long)(3 * HID) * KDIM; // 786432 per direction
    long long i = ((long long)blockIdx.x * blockDim.x + threadIdx.x) * 4;

    const float* src;
    __half* dst;
    if (i < NX)           { src = X   + i;             dst = g_Xh + i; }
    else if (i < NX + NW) { src = Wfw + (i - NX);      dst = g_Wh + (i - NX); }
    else                  { src = Wbw + (i - NX - NW); dst = g_Wh + (i - NX); }

    float4 v = __ldcs((const float4*)src);
    *(__half2*)dst       = __floats2half2_rn(v.x, v.y);
    *(__half2*)(dst + 2) = __floats2half2_rn(v.z, v.w);
}

// ===========================================================================
// GEMM path A: tcgen05 (only present in arch-specific pass)
//   TMEM double-buffered (256 cols): epilogue of tile i-1 overlaps MMA of i.
// ===========================================================================
#define GBM 128
#define GBN 128
#define GBK 64
#define NKCH (KDIM / GBK)        // 8
#define STAGES 3
#define STAGE_BYTES (GBM * 128)  // 16384 per operand per stage
#define SMEM_A_OFF 1024
#define SMEM_B_OFF (1024 + STAGES * STAGE_BYTES)
#define GEMM_SMEM  (1024 + 2 * STAGES * STAGE_BYTES)   // 99328
#define N_MTILE (MROWS / GBM)    // 256
#define N_NTILE (NCOLS / GBN)    // 24
#define N_TILES (N_MTILE * N_NTILE)  // 6144
#define GEMM_CTAS 296

#if HAS_TCGEN05
#define SMEM_SWIZZLE_128B(o) ((o) ^ (((o) >> 3) & 0x70))

static constexpr uint64_t SMEM_DESC_BASE_SW128 =
    (uint64_t(2) << 61) | (uint64_t(1) << 46) | (uint64_t(64) << 32) | (uint64_t(1) << 16);
#define MAKE_SMEM_DESC(base_addr) \
    (SMEM_DESC_BASE_SW128 | ((uint64_t)((base_addr) >> 4) & 0x3FFF))

#define MBARRIER_INIT(addr, cnt) \
    asm volatile("mbarrier.init.shared.b64 [%0], %1;" :: "r"((uint32_t)(addr)), "r"((uint32_t)(cnt)) : "memory")

#define MBARRIER_WAIT_PARITY(mbar_smem_addr, phase_parity) do { \
    uint32_t _mbar = (uint32_t)(mbar_smem_addr); \
    uint32_t _parity = (uint32_t)(phase_parity); \
    uint32_t _done; \
    asm volatile( \
        "{\n\t.reg .pred p;\n\t" \
        "mbarrier.try_wait.parity.acquire.cta.shared::cta.b64 p, [%1], %2;\n\t" \
        "selp.b32 %0, 1, 0, p;\n\t}" \
        : "=r"(_done) : "r"(_mbar), "r"(_parity) : "memory"); \
    if (!_done) { \
        asm volatile( \
            "{\n\t.reg .pred P1;\n\t" \
            "WAIT_LOOP_%=:\n\t" \
            "mbarrier.try_wait.parity.acquire.cta.shared::cta.b64 P1, [%0], %1, 0x989680;\n\t" \
            "@P1 bra.uni WAIT_DONE_%=;\n\t" \
            "bra.uni WAIT_LOOP_%=;\n\t" \
            "WAIT_DONE_%=:\n\t}" \
            :: "r"(_mbar), "r"(_parity) : "memory"); \
    } \
} while(0)

__device__ __forceinline__ uint32_t elect_one_pred() {
    uint32_t pred;
    asm volatile(
        "{\n\t.reg .pred p;\n\t"
        "elect.sync _|p, 0xFFFFFFFF;\n\t"
        "selp.b32 %0, 1, 0, p;\n\t}"
        : "=r"(pred));
    return pred;
}

#define TCGEN05_LD_32X32B_X32(r, tmem_addr) \
    asm volatile( \
        "tcgen05.ld.sync.aligned.32x32b.x32.b32 " \
        "{%0, %1, %2, %3, %4, %5, %6, %7, " \
        " %8, %9, %10, %11, %12, %13, %14, %15, " \
        " %16, %17, %18, %19, %20, %21, %22, %23, " \
        " %24, %25, %26, %27, %28, %29, %30, %31}, [%32];" \
        : "=r"((r)[0]),  "=r"((r)[1]),  "=r"((r)[2]),  "=r"((r)[3]), \
          "=r"((r)[4]),  "=r"((r)[5]),  "=r"((r)[6]),  "=r"((r)[7]), \
          "=r"((r)[8]),  "=r"((r)[9]),  "=r"((r)[10]), "=r"((r)[11]), \
          "=r"((r)[12]), "=r"((r)[13]), "=r"((r)[14]), "=r"((r)[15]), \
          "=r"((r)[16]), "=r"((r)[17]), "=r"((r)[18]), "=r"((r)[19]), \
          "=r"((r)[20]), "=r"((r)[21]), "=r"((r)[22]), "=r"((r)[23]), \
          "=r"((r)[24]), "=r"((r)[25]), "=r"((r)[26]), "=r"((r)[27]), \
          "=r"((r)[28]), "=r"((r)[29]), "=r"((r)[30]), "=r"((r)[31]) \
        : "r"(tmem_addr))

// idesc: dtype=F32 (1<<4), atype=btype=F16 (0), N/8<<17, M/16<<24
#define IDESC_F16 ((1u << 4) | ((GBN / 8u) << 17) | ((GBM / 16u) << 24))

__device__ __forceinline__ void mma_f16_ss(uint32_t d_tmem, uint64_t a_desc, uint64_t b_desc,
                                           uint32_t idesc, bool accum) {
    uint32_t en = accum ? 1u : 0u;
    asm volatile(
        "{\n\t.reg .pred p;\n\t"
        "setp.ne.u32 p, %4, 0;\n\t"
        "tcgen05.mma.cta_group::1.kind::f16 [%0], %1, %2, %3, {%5, %5, %5, %5}, p;\n\t}"
        :: "r"(d_tmem), "l"(a_desc), "l"(b_desc), "r"(idesc), "r"(en), "r"(0u)
        : "memory");
}

__device__ __forceinline__ void cp_async16(uint32_t dst, const void* src) {
    asm volatile("cp.async.cg.shared.global [%0], [%1], 16;" :: "r"(dst), "l"(src) : "memory");
}
__device__ __forceinline__ void cp_commit() {
    asm volatile("cp.async.commit_group;" ::: "memory");
}
template<int N> __device__ __forceinline__ void cp_wait() {
    asm volatile("cp.async.wait_group %0;" :: "n"(N) : "memory");
}

__device__ __forceinline__ void load_stage(uint32_t smem_base, int st, int kt,
                                           int m0, int n0, int tid)
{
    const __half* Asrc = g_Xh + (size_t)m0 * KDIM + kt * GBK;
    const __half* Bsrc = g_Wh + (size_t)n0 * KDIM + kt * GBK;
    uint32_t abase = smem_base + SMEM_A_OFF + st * STAGE_BYTES;
    uint32_t bbase = smem_base + SMEM_B_OFF + st * STAGE_BYTES;
#pragma unroll
    for (int i = 0; i < 8; i++) {
        int chunk = i * 128 + tid;        // 0..1023
        int row   = chunk >> 3;           // 0..127
        int c16   = chunk & 7;            // 16B column chunk
        uint32_t off = SMEM_SWIZZLE_128B((uint32_t)(row * 128 + c16 * 16));
        cp_async16(abase + off, Asrc + (size_t)row * KDIM + c16 * 8);
        cp_async16(bbase + off, Bsrc + (size_t)row * KDIM + c16 * 8);
    }
    cp_commit();
}

// Epilogue: TMEM fp32 -> fp16 -> streaming store to g_G.
__device__ __forceinline__ void epilogue_tile(uint32_t tmem_d, int m0, int n0,
                                              int wid, int lid)
{
    asm volatile("tcgen05.fence::after_thread_sync;" ::: "memory");
    const int m = m0 + wid * 32 + lid;
    __half* gout = g_G + (size_t)m * NCOLS + n0;
#pragma unroll
    for (int c0 = 0; c0 < GBN; c0 += 32) {
        uint32_t d[32];
        TCGEN05_LD_32X32B_X32(d, tmem_d + c0);
        asm volatile("tcgen05.wait::ld.sync.aligned;" ::: "memory");
        uint32_t hp[16];
#pragma unroll
        for (int c = 0; c < 16; c++) {
            __half2 h2 = __floats2half2_rn(__uint_as_float(d[2 * c]),
                                           __uint_as_float(d[2 * c + 1]));
            hp[c] = *(uint32_t*)&h2;
        }
#pragma unroll
        for (int q = 0; q < 4; q++) {
            uint4 v = make_uint4(hp[q * 4], hp[q * 4 + 1], hp[q * 4 + 2], hp[q * 4 + 3]);
            __stcs((uint4*)(gout + c0 + q * 8), v);
        }
    }
    asm volatile("tcgen05.fence::before_thread_sync;" ::: "memory");
}
#endif  // HAS_TCGEN05

#define MBAR(s) (smem_base + 16 + (s) * 8)

__global__ void __launch_bounds__(128, 2) __cluster_dims__(1, 1, 1) gemm_tc_kernel()
{
#if HAS_TCGEN05
    extern __shared__ char smem[];
    uint32_t smem_base = smem_to_u32(smem);
    const int tid = threadIdx.x;
    const int wid = tid >> 5;
    const int lid = tid & 31;

    if (tid < 4) MBARRIER_INIT(MBAR(tid), 1);   // 0-2: stage reuse, 3: tile-final
    if (wid == 0) {
        asm volatile("tcgen05.alloc.cta_group::1.sync.aligned.shared::cta.b32 [%0], %1;"
            :: "r"(smem_base), "r"(256u) : "memory");
        asm volatile("tcgen05.relinquish_alloc_permit.cta_group::1.sync.aligned;");
    }
    __syncthreads();

    uint32_t tmem;
    asm volatile("ld.shared.b32 %0, [%1];" : "=r"(tmem) : "r"(smem_base));

    int ph0 = 0, ph1 = 0, ph2 = 0, ph3 = 0;
    int buf = 0;
    int prev_m0 = 0, prev_n0 = 0;
    bool has_prev = false;

    for (int tile = blockIdx.x; tile < N_TILES; tile += GEMM_CTAS) {
        const int m0 = (tile / N_NTILE) * GBM;
        const int n0 = (tile % N_NTILE) * GBN;
        const uint32_t tmem_d = tmem + buf * 128;

        // Prologue: stage0 safe (its last MMA user, kt6 of prev tile, was
        // waited at kt7). Before overwriting stage1 (prev kt7) we must wait
        // the prev tile's final commit — which also makes its TMEM buffer
        // epilogue-ready.
        load_stage(smem_base, 0, 0, m0, n0, tid);
        if (has_prev) { MBARRIER_WAIT_PARITY(MBAR(3), ph3); ph3 ^= 1; }
        load_stage(smem_base, 1, 1, m0, n0, tid);

#pragma unroll
        for (int kt = 0; kt < NKCH; kt++) {
            const int st = kt % STAGES;
            if (kt == NKCH - 1) cp_wait<0>(); else cp_wait<1>();
            __syncthreads();
            asm volatile("fence.proxy.async.shared::cta;" ::: "memory");

            if (wid == 0) {
                if (elect_one_pred()) {
                    uint64_t ad = MAKE_SMEM_DESC(smem_base + SMEM_A_OFF + st * STAGE_BYTES);
                    uint64_t bd = MAKE_SMEM_DESC(smem_base + SMEM_B_OFF + st * STAGE_BYTES);
#pragma unroll
                    for (int k = 0; k < 4; k++)   // 4 x K=16 per 64-half chunk
                        mma_f16_ss(tmem_d, ad + k * 2, bd + k * 2, IDESC_F16,
                                   !(kt == 0 && k == 0));
                    asm volatile(
                        "tcgen05.commit.cta_group::1.mbarrier::arrive::one.shared::cluster.b64 [%0];"
                        :: "r"(MBAR(kt == NKCH - 1 ? 3 : st)) : "memory");
                }
            }

            // Guard smem stage (kt-1)%3 before load kt+2 overwrites it.
            if (kt >= 1) {
                const int ws = (kt - 1) % STAGES;
                if (ws == 0)      { MBARRIER_WAIT_PARITY(MBAR(0), ph0); ph0 ^= 1; }
                else if (ws == 1) { MBARRIER_WAIT_PARITY(MBAR(1), ph1); ph1 ^= 1; }
                else              { MBARRIER_WAIT_PARITY(MBAR(2), ph2); ph2 ^= 1; }
            }
            if (kt + 2 < NKCH)
                load_stage(smem_base, (kt + 2) % STAGES, kt + 2, m0, n0, tid);
        }

        // This tile's MMAs are in flight into tmem_d. Drain the PREVIOUS
        // tile's accumulator (other buffer) while they execute.
        if (has_prev) {
            epilogue_tile(tmem + (buf ^ 1) * 128, prev_m0, prev_n0, wid, lid);
            __syncthreads();
        }

        has_prev = true;
        prev_m0 = m0; prev_n0 = n0;
        buf ^= 1;
    }

    // Tail: drain the last tile.
    if (has_prev) {
        MBARRIER_WAIT_PARITY(MBAR(3), ph3); ph3 ^= 1;
        epilogue_tile(tmem + (buf ^ 1) * 128, prev_m0, prev_n0, wid, lid);
    }

    __syncthreads();
    if (wid == 0)
        asm volatile("tcgen05.dealloc.cta_group::1.sync.aligned.b32 %0, %1;" :: "r"(tmem), "r"(256u));
#endif  // HAS_TCGEN05
}

// ===========================================================================
// GEMM path B (fallback, baseline ISA): fp16 mma.sync.m16n8k16
// ===========================================================================
#define BM 128
#define BN 128
#define BK 32
#define HPAD 40   // 32 + 8 halves padding

__global__ __launch_bounds__(256) void gemm_fp16_kernel()
{
    __shared__ __half sA[BM][HPAD];
    __shared__ __half sB[BN][HPAD];

    const int tid  = threadIdx.x;
    const int n0   = blockIdx.x * BN;
    const int m0   = blockIdx.y * BM;

    const __half* Asrc = g_Xh + (size_t)m0 * KDIM;
    const __half* Bsrc = g_Wh + (size_t)n0 * KDIM;

    const int warp = tid >> 5;
    const int lane = tid & 31;
    const int wm   = warp >> 1;
    const int wn   = warp & 1;
    const int lr   = lane >> 2;
    const int lc   = lane & 3;

    float4 ra[2], rb[2];

#pragma unroll
    for (int i = 0; i < 2; i++) {
        int slot = tid + i * 256;
        int row  = slot >> 2;
        int c8   = slot & 3;
        ra[i] = *(const float4*)(Asrc + (size_t)row * KDIM + c8 * 8);
        rb[i] = *(const float4*)(Bsrc + (size_t)row * KDIM + c8 * 8);
    }
#pragma unroll
    for (int i = 0; i < 2; i++) {
        int slot = tid + i * 256;
        int row  = slot >> 2;
        int c8   = slot & 3;
        *(float4*)&sA[row][c8 * 8] = ra[i];
        *(float4*)&sB[row][c8 * 8] = rb[i];
    }
    __syncthreads();

    float acc[2][8][4];
#pragma unroll
    for (int mt = 0; mt < 2; mt++)
#pragma unroll
        for (int nt = 0; nt < 8; nt++)
#pragma unroll
            for (int r = 0; r < 4; r++) acc[mt][nt][r] = 0.0f;

    const int NK = KDIM / BK;  // 16
    for (int kt = 0; kt < NK; kt++) {
        if (kt < NK - 1) {
#pragma unroll
            for (int i = 0; i < 2; i++) {
                int slot = tid + i * 256;
                int row  = slot >> 2;
                int c8   = slot & 3;
                ra[i] = *(const float4*)(Asrc + (size_t)row * KDIM + (kt + 1) * BK + c8 * 8);
                rb[i] = *(const float4*)(Bsrc + (size_t)row * KDIM + (kt + 1) * BK + c8 * 8);
            }
        }

#pragma unroll
        for (int ks = 0; ks < 2; ks++) {
            const int kc = ks * 16 + lc * 2;
            uint32_t afr[2][4];
            uint32_t bfr[8][2];
#pragma unroll
            for (int mt = 0; mt < 2; mt++) {
                int r = wm * 32 + mt * 16 + lr;
                afr[mt][0] = *(const uint32_t*)&sA[r    ][kc    ];
                afr[mt][1] = *(const uint32_t*)&sA[r + 8][kc    ];
                afr[mt][2] = *(const uint32_t*)&sA[r    ][kc + 8];
                afr[mt][3] = *(const uint32_t*)&sA[r + 8][kc + 8];
            }
#pragma unroll
            for (int nt = 0; nt < 8; nt++) {
                int nr = wn * 64 + nt * 8 + lr;
                bfr[nt][0] = *(const uint32_t*)&sB[nr][kc    ];
                bfr[nt][1] = *(const uint32_t*)&sB[nr][kc + 8];
            }
#pragma unroll
            for (int mt = 0; mt < 2; mt++)
#pragma unroll
                for (int nt = 0; nt < 8; nt++)
                    asm volatile(
                        "mma.sync.aligned.m16n8k16.row.col.f32.f16.f16.f32 "
                        "{%0,%1,%2,%3}, {%4,%5,%6,%7}, {%8,%9}, {%0,%1,%2,%3};"
                        : "+f"(acc[mt][nt][0]), "+f"(acc[mt][nt][1]),
                          "+f"(acc[mt][nt][2]), "+f"(acc[mt][nt][3])
                        : "r"(afr[mt][0]), "r"(afr[mt][1]), "r"(afr[mt][2]), "r"(afr[mt][3]),
                          "r"(bfr[nt][0]), "r"(bfr[nt][1]));
        }

        __syncthreads();
        if (kt < NK - 1) {
#pragma unroll
            for (int i = 0; i < 2; i++) {
                int slot = tid + i * 256;
                int row  = slot >> 2;
                int c8   = slot & 3;
                *(float4*)&sA[row][c8 * 8] = ra[i];
                *(float4*)&sB[row][c8 * 8] = rb[i];
            }
            __syncthreads();
        }
    }

#pragma unroll
    for (int mt = 0; mt < 2; mt++) {
#pragma unroll
        for (int nt = 0; nt < 8; nt++) {
            int r0  = m0 + wm * 32 + mt * 16 + lr;
            int col = n0 + wn * 64 + nt * 8 + lc * 2;
            __half2 h0 = __floats2half2_rn(acc[mt][nt][0], acc[mt][nt][1]);
            __half2 h1 = __floats2half2_rn(acc[mt][nt][2], acc[mt][nt][3]);
            *(__half2*)(g_G + (size_t)r0 * NCOLS + col)       = h0;
            *(__half2*)(g_G + (size_t)(r0 + 8) * NCOLS + col) = h1;
        }
    }
}

// ===========================================================================
// Chunked scan: 3 passes (fp16 gate reads, streaming).
// ===========================================================================
#define SCH 8   // inner prefetch chunk

__global__ __launch_bounds__(256) void scan_phase1(
    const float* __restrict__ bfw,
    const float* __restrict__ bbw)
{
    const int t   = blockIdx.x * 256 + threadIdx.x;   // 0..131071
    const int h   = t & 511;
    const int c   = (t >> 9) & 7;
    const int bi  = (t >> 12) & 15;
    const int dir = t >> 16;
    const int lane = dir * 8192 + bi * 512 + h;

    const float* bias = dir ? bbw : bfw;
    const float bz = bias[h];
    const float bf = bias[HID + h];

    const int s0 = dir ? (SEQ - 1 - c * CHLEN) : (c * CHLEN);
    const long long step = dir ? -(long long)(BATCH * NCOLS) : (long long)(BATCH * NCOLS);
    const __half* gp = g_G + ((long long)(s0 * BATCH + bi)) * NCOLS + dir * 3 * HID + h;

    float zc[SCH], fc[SCH];
#pragma unroll
    for (int j = 0; j < SCH; j++) {
        zc[j] = __half2float(__ldcs(gp));
        fc[j] = __half2float(__ldcs(gp + HID));
        gp += step;
    }

    float hs = 0.0f, A = 1.0f;
    const int NIT = CHLEN / SCH;  // 32
    for (int it = 0; it < NIT; it++) {
        float zn[SCH], fn[SCH];
        if (it < NIT - 1) {
#pragma unroll
            for (int j = 0; j < SCH; j++) {
                zn[j] = __half2float(__ldcs(gp));
                fn[j] = __half2float(__ldcs(gp + HID));
                gp += step;
            }
        }
#pragma unroll
        for (int j = 0; j < SCH; j++) {
            float z = tanh_(zc[j] + bz);
            float f = sigm_(fc[j] + bf);
            hs = fmaf(f, z - hs, hs);
            A *= (1.0f - f);
        }
#pragma unroll
        for (int j = 0; j < SCH; j++) { zc[j] = zn[j]; fc[j] = fn[j]; }
    }

    g_A[c * NLANE + lane] = A;
    g_C[c * NLANE + lane] = hs;
}

__global__ __launch_bounds__(256) void scan_combine()
{
    const int lane = blockIdx.x * 256 + threadIdx.x;  // 0..16383
    float H = 0.0f;
#pragma unroll
    for (int c = 0; c < NCHK; c++) {
        g_Hin[c * NLANE + lane] = H;
        H = g_A[c * NLANE + lane] * H + g_C[c * NLANE + lane];
    }
}

__global__ __launch_bounds__(256) void scan_phase3(
    const float* __restrict__ bfw,
    const float* __restrict__ bbw,
    float* __restrict__ Y)
{
    const int t   = blockIdx.x * 256 + threadIdx.x;   // 0..131071
    const int h   = t & 511;
    const int c   = (t >> 9) & 7;
    const int bi  = (t >> 12) & 15;
    const int dir = t >> 16;
    const int lane = dir * 8192 + bi * 512 + h;

    const float* bias = dir ? bbw : bfw;
    const float bz = bias[h];
    const float bf = bias[HID + h];
    const float bo = bias[2 * HID + h];

    const int s0 = dir ? (SEQ - 1 - c * CHLEN) : (c * CHLEN);
    const long long step  = dir ? -(long long)(BATCH * NCOLS)   : (long long)(BATCH * NCOLS);
    const long long ystep = dir ? -(long long)(BATCH * 2 * HID) : (long long)(BATCH * 2 * HID);
    const __half* gp = g_G + ((long long)(s0 * BATCH + bi)) * NCOLS + dir * 3 * HID + h;
    float*        yp = Y   + ((long long)(s0 * BATCH + bi)) * (2 * HID) + dir * HID + h;

    float zc[SCH], fc[SCH], oc[SCH];
#pragma unroll
    for (int j = 0; j < SCH; j++) {
        zc[j] = __half2float(__ldcs(gp));
        fc[j] = __half2float(__ldcs(gp + HID));
        oc[j] = __half2float(__ldcs(gp + 2 * HID));
        gp += step;
    }

    float hs = g_Hin[c * NLANE + lane];
    const int NIT = CHLEN / SCH;  // 32
    for (int it = 0; it < NIT; it++) {
        float zn[SCH], fn[SCH], on[SCH];
        if (it < NIT - 1) {
#pragma unroll
            for (int j = 0; j < SCH; j++) {
                zn[j] = __half2float(__ldcs(gp));
                fn[j] = __half2float(__ldcs(gp + HID));
                on[j] = __half2float(__ldcs(gp + 2 * HID));
                gp += step;
            }
        }
#pragma unroll
        for (int j = 0; j < SCH; j++) {
            float z = tanh_(zc[j] + bz);
            float f = sigm_(fc[j] + bf);
            float o = sigm_(oc[j] + bo);
            hs = fmaf(f, z - hs, hs);
            __stcs(yp, o * hs);
            yp += ystep;
        }
#pragma unroll
        for (int j = 0; j < SCH; j++) { zc[j] = zn[j]; fc[j] = fn[j]; oc[j] = on[j]; }
    }
}

// ---------------------------------------------------------------------------
// Launch
// ---------------------------------------------------------------------------
extern "C" void kernel_launch(void* const* d_in, const int* in_sizes, int n_in,
                              void* d_out, int out_size)
{
    const float* X   = (const float*)d_in[0];
    const float* Wfw = (const float*)d_in[1];
    const float* bfw = (const float*)d_in[2];
    const float* Wbw = (const float*)d_in[3];
    const float* bbw = (const float*)d_in[4];
    float* Y = (float*)d_out;

    cudaFuncAttributes pa;
    bool use_tc = false;
    if (cudaFuncGetAttributes(&pa, probe_kernel) == cudaSuccess)
        use_tc = (pa.sharedSizeBytes >= 4096);

    cvt_kernel<<<17920, 256>>>(X, Wfw, Wbw);

    if (use_tc) {
        cudaFuncSetAttribute(gemm_tc_kernel, cudaFuncAttributeMaxDynamicSharedMemorySize, GEMM_SMEM);
        gemm_tc_kernel<<<GEMM_CTAS, 128, GEMM_SMEM>>>();
    } else {
        dim3 ggrid(NCOLS / BN, MROWS / BM);   // (24, 256)
        gemm_fp16_kernel<<<ggrid, 256>>>();
    }

    scan_phase1<<<131072 / 256, 256>>>(bfw, bbw);
    scan_combine<<<16384 / 256, 256>>>();
    scan_phase3<<<131072 / 256, 256>>>(bfw, bbw, Y);
}

// round 9
// speedup vs baseline: 4.8700x; 1.0082x over previous
#include <cuda_runtime.h>
#include <cuda_fp16.h>
#include <cuda_bf16.h>
#include <cstdint>

// ---------------------------------------------------------------------------
// Problem constants
// ---------------------------------------------------------------------------
#define SEQ   2048
#define BATCH 16
#define DIN   512
#define HID   512
#define MROWS (SEQ*BATCH)       // 32768
#define NCOLS (3*HID*2)         // 3072
#define KDIM  DIN               // 512

// Feature gate: tcgen05 only exists in an arch-specific (sm_103a/sm_100a) pass.
#if defined(__CUDA_ARCH__) && (defined(__CUDA_ARCH_FEAT_SM103_ALL) || defined(__CUDA_ARCH_FEAT_SM100_ALL))
#define HAS_TCGEN05 1
#else
#define HAS_TCGEN05 0
#endif

// Scratch (static device arrays; no allocation allowed)
__device__ __half g_G[(size_t)MROWS * NCOLS];   // pre-activation gates (fp16)
__device__ __half g_Xh[(size_t)MROWS * KDIM];   // X in fp16
__device__ __half g_Wh[(size_t)NCOLS * KDIM];   // [W_fw; W_bw] in fp16

// Chunked-scan aggregates: 16384 lanes x 8 chunks, layout [chunk][lane]
#define NLANE 16384
#define NCHK  8
#define CHLEN (SEQ / NCHK)      // 256
__device__ float g_A[NCHK * NLANE];
__device__ float g_C[NCHK * NLANE];
__device__ float g_Hin[NCHK * NLANE];

// ---------------------------------------------------------------------------
// Probe kernel: static smem size tells the host whether the loaded device
// code came from the arch-specific (tcgen05-capable) pass.
// ---------------------------------------------------------------------------
__global__ void probe_kernel(float* p) {
#if HAS_TCGEN05
    __shared__ volatile float s[2048];
#else
    __shared__ volatile float s[64];
#endif
    s[threadIdx.x & 63] = p[0];
    p[1] = s[(threadIdx.x + 1) & 63];
}

// ---------------------------------------------------------------------------
// Common helpers
// ---------------------------------------------------------------------------
__device__ __forceinline__ uint32_t smem_to_u32(const void* p) {
    uint32_t a;
    asm("{ .reg .u64 t; cvta.to.shared.u64 t, %1; cvt.u32.u64 %0, t; }" : "=r"(a) : "l"(p));
    return a;
}

__device__ __forceinline__ float ex2f(float x) {
    float y; asm("ex2.approx.ftz.f32 %0, %1;" : "=f"(y) : "f"(x)); return y;
}
__device__ __forceinline__ float rcpf(float x) {
    float y; asm("rcp.approx.ftz.f32 %0, %1;" : "=f"(y) : "f"(x)); return y;
}
__device__ __forceinline__ float sigm_(float x) {
    return rcpf(1.0f + ex2f(-1.4426950408889634f * x));
}
__device__ __forceinline__ float tanh_(float x) {
    return fmaf(2.0f, rcpf(1.0f + ex2f(-2.8853900817779268f * x)), -1.0f);
}

// ---------------------------------------------------------------------------
// Kernel 0: fp32 -> fp16 conversion (X, W_fw, W_bw)
// ---------------------------------------------------------------------------
__global__ __launch_bounds__(256) void cvt_kernel(
    const float* __restrict__ X,
    const float* __restrict__ Wfw,
    const float* __restrict__ Wbw)
{
    const long long NX = (long long)MROWS * KDIM;     // 16777216
    const long long NW = (long long)(3 * HID) * KDIM; // 786432 per direction
    long long i = ((long long)blockIdx.x * blockDim.x + threadIdx.x) * 4;

    const float* src;
    __half* dst;
    if (i < NX)           { src = X   + i;             dst = g_Xh + i; }
    else if (i < NX + NW) { src = Wfw + (i - NX);      dst = g_Wh + (i - NX); }
    else                  { src = Wbw + (i - NX - NW); dst = g_Wh + (i - NX); }

    float4 v = __ldcs((const float4*)src);
    *(__half2*)dst       = __floats2half2_rn(v.x, v.y);
    *(__half2*)(dst + 2) = __floats2half2_rn(v.z, v.w);
}

// ===========================================================================
// GEMM path A: tcgen05, M=128 x N=256 tiles (cuts L2 operand traffic 25%),
// 1 CTA/SM, 4-stage cp.async pipeline, TMEM double-buffered epilogue overlap.
// ===========================================================================
#define GBM 128
#define GBN 256
#define GBK 64
#define NKCH (KDIM / GBK)        // 8
#define STAGES 4
#define STAGE_A 16384            // 128 rows x 128B
#define STAGE_B 32768            // 256 rows x 128B
#define SMEM_A_OFF 1024
#define SMEM_B_OFF (1024 + STAGES * STAGE_A)          // 66560
#define GEMM_SMEM  (SMEM_B_OFF + STAGES * STAGE_B)    // 197632
#define N_MTILE (MROWS / GBM)    // 256
#define N_NTILE (NCOLS / GBN)    // 12
#define N_TILES (N_MTILE * N_NTILE)  // 3072
#define GEMM_CTAS 148
#define GEMM_THREADS 256

#if HAS_TCGEN05
#define SMEM_SWIZZLE_128B(o) ((o) ^ (((o) >> 3) & 0x70))

static constexpr uint64_t SMEM_DESC_BASE_SW128 =
    (uint64_t(2) << 61) | (uint64_t(1) << 46) | (uint64_t(64) << 32) | (uint64_t(1) << 16);
#define MAKE_SMEM_DESC(base_addr) \
    (SMEM_DESC_BASE_SW128 | ((uint64_t)((base_addr) >> 4) & 0x3FFF))

#define MBARRIER_INIT(addr, cnt) \
    asm volatile("mbarrier.init.shared.b64 [%0], %1;" :: "r"((uint32_t)(addr)), "r"((uint32_t)(cnt)) : "memory")

__device__ __forceinline__ void mbar_wait(uint32_t mbar, int parity) {
    uint32_t done;
    asm volatile(
        "{\n\t.reg .pred p;\n\t"
        "mbarrier.try_wait.parity.acquire.cta.shared::cta.b64 p, [%1], %2;\n\t"
        "selp.b32 %0, 1, 0, p;\n\t}"
        : "=r"(done) : "r"(mbar), "r"((uint32_t)parity) : "memory");
    if (!done) {
        asm volatile(
            "{\n\t.reg .pred P1;\n\t"
            "WAIT_LOOP_%=:\n\t"
            "mbarrier.try_wait.parity.acquire.cta.shared::cta.b64 P1, [%0], %1, 0x989680;\n\t"
            "@P1 bra.uni WAIT_DONE_%=;\n\t"
            "bra.uni WAIT_LOOP_%=;\n\t"
            "WAIT_DONE_%=:\n\t}"
            :: "r"(mbar), "r"((uint32_t)parity) : "memory");
    }
}

__device__ __forceinline__ uint32_t elect_one_pred() {
    uint32_t pred;
    asm volatile(
        "{\n\t.reg .pred p;\n\t"
        "elect.sync _|p, 0xFFFFFFFF;\n\t"
        "selp.b32 %0, 1, 0, p;\n\t}"
        : "=r"(pred));
    return pred;
}

#define TCGEN05_LD_32X32B_X32(r, tmem_addr) \
    asm volatile( \
        "tcgen05.ld.sync.aligned.32x32b.x32.b32 " \
        "{%0, %1, %2, %3, %4, %5, %6, %7, " \
        " %8, %9, %10, %11, %12, %13, %14, %15, " \
        " %16, %17, %18, %19, %20, %21, %22, %23, " \
        " %24, %25, %26, %27, %28, %29, %30, %31}, [%32];" \
        : "=r"((r)[0]),  "=r"((r)[1]),  "=r"((r)[2]),  "=r"((r)[3]), \
          "=r"((r)[4]),  "=r"((r)[5]),  "=r"((r)[6]),  "=r"((r)[7]), \
          "=r"((r)[8]),  "=r"((r)[9]),  "=r"((r)[10]), "=r"((r)[11]), \
          "=r"((r)[12]), "=r"((r)[13]), "=r"((r)[14]), "=r"((r)[15]), \
          "=r"((r)[16]), "=r"((r)[17]), "=r"((r)[18]), "=r"((r)[19]), \
          "=r"((r)[20]), "=r"((r)[21]), "=r"((r)[22]), "=r"((r)[23]), \
          "=r"((r)[24]), "=r"((r)[25]), "=r"((r)[26]), "=r"((r)[27]), \
          "=r"((r)[28]), "=r"((r)[29]), "=r"((r)[30]), "=r"((r)[31]) \
        : "r"(tmem_addr))

// idesc: dtype=F32 (1<<4), atype=btype=F16 (0), N=128 -> N/8<<17, M=128 -> M/16<<24
#define IDESC_F16 ((1u << 4) | ((128u / 8u) << 17) | ((128u / 16u) << 24))

__device__ __forceinline__ void mma_f16_ss(uint32_t d_tmem, uint64_t a_desc, uint64_t b_desc,
                                           uint32_t idesc, bool accum) {
    uint32_t en = accum ? 1u : 0u;
    asm volatile(
        "{\n\t.reg .pred p;\n\t"
        "setp.ne.u32 p, %4, 0;\n\t"
        "tcgen05.mma.cta_group::1.kind::f16 [%0], %1, %2, %3, {%5, %5, %5, %5}, p;\n\t}"
        :: "r"(d_tmem), "l"(a_desc), "l"(b_desc), "r"(idesc), "r"(en), "r"(0u)
        : "memory");
}

__device__ __forceinline__ void cp_async16(uint32_t dst, const void* src) {
    asm volatile("cp.async.cg.shared.global [%0], [%1], 16;" :: "r"(dst), "l"(src) : "memory");
}
__device__ __forceinline__ void cp_commit() {
    asm volatile("cp.async.commit_group;" ::: "memory");
}
template<int N> __device__ __forceinline__ void cp_wait() {
    asm volatile("cp.async.wait_group %0;" :: "n"(N) : "memory");
}

// Load one K-chunk (A: 128x64 halfs, B: 256x64 halfs) into stage st.
__device__ __forceinline__ void load_stage(uint32_t smem_base, int st, int kt,
                                           int m0, int n0, int tid)
{
    const __half* Asrc = g_Xh + (size_t)m0 * KDIM + kt * GBK;
    const __half* Bsrc = g_Wh + (size_t)n0 * KDIM + kt * GBK;
    uint32_t abase = smem_base + SMEM_A_OFF + st * STAGE_A;
    uint32_t bbase = smem_base + SMEM_B_OFF + st * STAGE_B;
#pragma unroll
    for (int i = 0; i < 4; i++) {                 // A: 1024 16B-chunks
        int chunk = i * GEMM_THREADS + tid;
        int row   = chunk >> 3;
        int c16   = chunk & 7;
        uint32_t off = SMEM_SWIZZLE_128B((uint32_t)(row * 128 + c16 * 16));
        cp_async16(abase + off, Asrc + (size_t)row * KDIM + c16 * 8);
    }
#pragma unroll
    for (int i = 0; i < 8; i++) {                 // B: 2048 16B-chunks
        int chunk = i * GEMM_THREADS + tid;
        int row   = chunk >> 3;
        int c16   = chunk & 7;
        uint32_t off = SMEM_SWIZZLE_128B((uint32_t)(row * 128 + c16 * 16));
        cp_async16(bbase + off, Bsrc + (size_t)row * KDIM + c16 * 8);
    }
    cp_commit();
}

// Epilogue: TMEM fp32 (128 lanes x 256 cols) -> fp16 -> streaming store.
// Warps 0-3 handle cols [0,128), warps 4-7 cols [128,256); each warp its
// 32-lane subpartition.
__device__ __forceinline__ void epilogue_tile(uint32_t tmem_d, int m0, int n0,
                                              int wid, int lid)
{
    asm volatile("tcgen05.fence::after_thread_sync;" ::: "memory");
    const int sub     = wid & 3;
    const int colhalf = wid >> 2;
    const int m = m0 + sub * 32 + lid;
    __half* gout = g_G + (size_t)m * NCOLS + n0 + colhalf * 128;
    const uint32_t tbase = tmem_d + colhalf * 128;
#pragma unroll
    for (int c0 = 0; c0 < 128; c0 += 32) {
        uint32_t d[32];
        TCGEN05_LD_32X32B_X32(d, tbase + c0);
        asm volatile("tcgen05.wait::ld.sync.aligned;" ::: "memory");
        uint32_t hp[16];
#pragma unroll
        for (int c = 0; c < 16; c++) {
            __half2 h2 = __floats2half2_rn(__uint_as_float(d[2 * c]),
                                           __uint_as_float(d[2 * c + 1]));
            hp[c] = *(uint32_t*)&h2;
        }
#pragma unroll
        for (int q = 0; q < 4; q++) {
            uint4 v = make_uint4(hp[q * 4], hp[q * 4 + 1], hp[q * 4 + 2], hp[q * 4 + 3]);
            __stcs((uint4*)(gout + c0 + q * 8), v);
        }
    }
    asm volatile("tcgen05.fence::before_thread_sync;" ::: "memory");
}
#endif  // HAS_TCGEN05

#define MBAR(s) (smem_base + 16 + (s) * 8)
#define SLOT_FINAL 4

__global__ void __launch_bounds__(GEMM_THREADS, 1) __cluster_dims__(1, 1, 1) gemm_tc_kernel()
{
#if HAS_TCGEN05
    extern __shared__ char smem[];
    uint32_t smem_base = smem_to_u32(smem);
    const int tid = threadIdx.x;
    const int wid = tid >> 5;
    const int lid = tid & 31;

    if (tid < 5) MBARRIER_INIT(MBAR(tid), 1);   // 0-3: stage reuse, 4: tile-final
    if (wid == 0) {
        asm volatile("tcgen05.alloc.cta_group::1.sync.aligned.shared::cta.b32 [%0], %1;"
            :: "r"(smem_base), "r"(512u) : "memory");
        asm volatile("tcgen05.relinquish_alloc_permit.cta_group::1.sync.aligned;");
    }
    __syncthreads();

    uint32_t tmem;
    asm volatile("ld.shared.b32 %0, [%1];" : "=r"(tmem) : "r"(smem_base));

    int ph[5] = {0, 0, 0, 0, 0};
    int buf = 0;
    int prev_m0 = 0, prev_n0 = 0;
    bool has_prev = false;

    for (int tile = blockIdx.x; tile < N_TILES; tile += GEMM_CTAS) {
        const int m0 = (tile / N_NTILE) * GBM;
        const int n0 = (tile % N_NTILE) * GBN;
        const uint32_t tmem_d = tmem + buf * 256;

        // Prologue: stages 0,1 safe (their prev chunks 4,5 waited at kt=5,6).
        // Stage 2 (prev chunk 6) waited at kt=7. Stage 3 (prev chunk 7) is
        // guarded by FINAL, which also makes prev TMEM buffer epilogue-ready.
        load_stage(smem_base, 0, 0, m0, n0, tid);
        load_stage(smem_base, 1, 1, m0, n0, tid);
        if (has_prev) { mbar_wait(MBAR(SLOT_FINAL), ph[SLOT_FINAL]); ph[SLOT_FINAL] ^= 1; }
        load_stage(smem_base, 2, 2, m0, n0, tid);

#pragma unroll
        for (int kt = 0; kt < NKCH; kt++) {
            const int st = kt % STAGES;
            if (kt == NKCH - 1)      cp_wait<0>();
            else if (kt == NKCH - 2) cp_wait<1>();
            else                     cp_wait<2>();
            __syncthreads();
            asm volatile("fence.proxy.async.shared::cta;" ::: "memory");

            if (wid == 0) {
                if (elect_one_pred()) {
                    uint64_t ad = MAKE_SMEM_DESC(smem_base + SMEM_A_OFF + st * STAGE_A);
                    uint64_t bd = MAKE_SMEM_DESC(smem_base + SMEM_B_OFF + st * STAGE_B);
#pragma unroll
                    for (int nh = 0; nh < 2; nh++)
#pragma unroll
                        for (int k = 0; k < 4; k++)   // 4 x K=16 per 64-half chunk
                            mma_f16_ss(tmem_d + nh * 128,
                                       ad + k * 2,
                                       bd + nh * 1024 + k * 2,   // +128 B-rows
                                       IDESC_F16,
                                       !(kt == 0 && k == 0));
                    asm volatile(
                        "tcgen05.commit.cta_group::1.mbarrier::arrive::one.shared::cluster.b64 [%0];"
                        :: "r"(MBAR(kt == NKCH - 1 ? SLOT_FINAL : st)) : "memory");
                }
            }

            // Guard smem stage (kt-1)%4 (its MMA done) before chunk kt+3 overwrites it.
            if (kt >= 1) {
                const int ws = (kt - 1) % STAGES;
                mbar_wait(MBAR(ws), ph[ws]); ph[ws] ^= 1;
            }
            if (kt + 3 < NKCH)
                load_stage(smem_base, (kt + 3) % STAGES, kt + 3, m0, n0, tid);
        }

        // This tile's MMAs are in flight into tmem_d. Drain the PREVIOUS
        // tile's accumulator (other buffer) while they execute.
        if (has_prev) {
            epilogue_tile(tmem + (buf ^ 1) * 256, prev_m0, prev_n0, wid, lid);
        }

        has_prev = true;
        prev_m0 = m0; prev_n0 = n0;
        buf ^= 1;
    }

    // Tail: drain the last tile.
    if (has_prev) {
        mbar_wait(MBAR(SLOT_FINAL), ph[SLOT_FINAL]); ph[SLOT_FINAL] ^= 1;
        epilogue_tile(tmem + (buf ^ 1) * 256, prev_m0, prev_n0, wid, lid);
    }

    __syncthreads();
    if (wid == 0)
        asm volatile("tcgen05.dealloc.cta_group::1.sync.aligned.b32 %0, %1;" :: "r"(tmem), "r"(512u));
#endif  // HAS_TCGEN05
}

// ===========================================================================
// GEMM path B (fallback, baseline ISA): fp16 mma.sync.m16n8k16
// ===========================================================================
#define BM 128
#define BN 128
#define BK 32
#define HPAD 40   // 32 + 8 halves padding

__global__ __launch_bounds__(256) void gemm_fp16_kernel()
{
    __shared__ __half sA[BM][HPAD];
    __shared__ __half sB[BN][HPAD];

    const int tid  = threadIdx.x;
    const int n0   = blockIdx.x * BN;
    const int m0   = blockIdx.y * BM;

    const __half* Asrc = g_Xh + (size_t)m0 * KDIM;
    const __half* Bsrc = g_Wh + (size_t)n0 * KDIM;

    const int warp = tid >> 5;
    const int lane = tid & 31;
    const int wm   = warp >> 1;
    const int wn   = warp & 1;
    const int lr   = lane >> 2;
    const int lc   = lane & 3;

    float4 ra[2], rb[2];

#pragma unroll
    for (int i = 0; i < 2; i++) {
        int slot = tid + i * 256;
        int row  = slot >> 2;
        int c8   = slot & 3;
        ra[i] = *(const float4*)(Asrc + (size_t)row * KDIM + c8 * 8);
        rb[i] = *(const float4*)(Bsrc + (size_t)row * KDIM + c8 * 8);
    }
#pragma unroll
    for (int i = 0; i < 2; i++) {
        int slot = tid + i * 256;
        int row  = slot >> 2;
        int c8   = slot & 3;
        *(float4*)&sA[row][c8 * 8] = ra[i];
        *(float4*)&sB[row][c8 * 8] = rb[i];
    }
    __syncthreads();

    float acc[2][8][4];
#pragma unroll
    for (int mt = 0; mt < 2; mt++)
#pragma unroll
        for (int nt = 0; nt < 8; nt++)
#pragma unroll
            for (int r = 0; r < 4; r++) acc[mt][nt][r] = 0.0f;

    const int NK = KDIM / BK;  // 16
    for (int kt = 0; kt < NK; kt++) {
        if (kt < NK - 1) {
#pragma unroll
            for (int i = 0; i < 2; i++) {
                int slot = tid + i * 256;
                int row  = slot >> 2;
                int c8   = slot & 3;
                ra[i] = *(const float4*)(Asrc + (size_t)row * KDIM + (kt + 1) * BK + c8 * 8);
                rb[i] = *(const float4*)(Bsrc + (size_t)row * KDIM + (kt + 1) * BK + c8 * 8);
            }
        }

#pragma unroll
        for (int ks = 0; ks < 2; ks++) {
            const int kc = ks * 16 + lc * 2;
            uint32_t afr[2][4];
            uint32_t bfr[8][2];
#pragma unroll
            for (int mt = 0; mt < 2; mt++) {
                int r = wm * 32 + mt * 16 + lr;
                afr[mt][0] = *(const uint32_t*)&sA[r    ][kc    ];
                afr[mt][1] = *(const uint32_t*)&sA[r + 8][kc    ];
                afr[mt][2] = *(const uint32_t*)&sA[r    ][kc + 8];
                afr[mt][3] = *(const uint32_t*)&sA[r + 8][kc + 8];
            }
#pragma unroll
            for (int nt = 0; nt < 8; nt++) {
                int nr = wn * 64 + nt * 8 + lr;
                bfr[nt][0] = *(const uint32_t*)&sB[nr][kc    ];
                bfr[nt][1] = *(const uint32_t*)&sB[nr][kc + 8];
            }
#pragma unroll
            for (int mt = 0; mt < 2; mt++)
#pragma unroll
                for (int nt = 0; nt < 8; nt++)
                    asm volatile(
                        "mma.sync.aligned.m16n8k16.row.col.f32.f16.f16.f32 "
                        "{%0,%1,%2,%3}, {%4,%5,%6,%7}, {%8,%9}, {%0,%1,%2,%3};"
                        : "+f"(acc[mt][nt][0]), "+f"(acc[mt][nt][1]),
                          "+f"(acc[mt][nt][2]), "+f"(acc[mt][nt][3])
                        : "r"(afr[mt][0]), "r"(afr[mt][1]), "r"(afr[mt][2]), "r"(afr[mt][3]),
                          "r"(bfr[nt][0]), "r"(bfr[nt][1]));
        }

        __syncthreads();
        if (kt < NK - 1) {
#pragma unroll
            for (int i = 0; i < 2; i++) {
                int slot = tid + i * 256;
                int row  = slot >> 2;
                int c8   = slot & 3;
                *(float4*)&sA[row][c8 * 8] = ra[i];
                *(float4*)&sB[row][c8 * 8] = rb[i];
            }
            __syncthreads();
        }
    }

#pragma unroll
    for (int mt = 0; mt < 2; mt++) {
#pragma unroll
        for (int nt = 0; nt < 8; nt++) {
            int r0  = m0 + wm * 32 + mt * 16 + lr;
            int col = n0 + wn * 64 + nt * 8 + lc * 2;
            __half2 h0 = __floats2half2_rn(acc[mt][nt][0], acc[mt][nt][1]);
            __half2 h1 = __floats2half2_rn(acc[mt][nt][2], acc[mt][nt][3]);
            *(__half2*)(g_G + (size_t)r0 * NCOLS + col)       = h0;
            *(__half2*)(g_G + (size_t)(r0 + 8) * NCOLS + col) = h1;
        }
    }
}

// ===========================================================================
// Chunked scan: 3 passes. Each thread handles an (h, h+1) pair via half2.
// 65536 threads for phases 1/3.
// ===========================================================================
#define SCH 8   // inner prefetch chunk

__global__ __launch_bounds__(256) void scan_phase1(
    const float* __restrict__ bfw,
    const float* __restrict__ bbw)
{
    const int t    = blockIdx.x * 256 + threadIdx.x;   // 0..65535
    const int h    = (t & 255) * 2;
    const int c    = (t >> 8) & 7;
    const int bi   = (t >> 11) & 15;
    const int dir  = t >> 15;
    const int lane = dir * 8192 + bi * 512 + h;

    const float* bias = dir ? bbw : bfw;
    const float2 bz = *(const float2*)(bias + h);
    const float2 bf = *(const float2*)(bias + HID + h);

    const int s0 = dir ? (SEQ - 1 - c * CHLEN) : (c * CHLEN);
    const long long step2 = (dir ? -(long long)(BATCH * NCOLS) : (long long)(BATCH * NCOLS)) / 2;
    const __half2* gp = (const __half2*)(g_G + ((long long)(s0 * BATCH + bi)) * NCOLS
                                         + dir * 3 * HID + h);

    __half2 zc[SCH], fc[SCH];
#pragma unroll
    for (int j = 0; j < SCH; j++) {
        zc[j] = __ldcs(gp);
        fc[j] = __ldcs(gp + HID / 2);
        gp += step2;
    }

    float hs0 = 0.0f, hs1 = 0.0f, A0 = 1.0f, A1 = 1.0f;
    const int NIT = CHLEN / SCH;  // 32
    for (int it = 0; it < NIT; it++) {
        __half2 zn[SCH], fn[SCH];
        if (it < NIT - 1) {
#pragma unroll
            for (int j = 0; j < SCH; j++) {
                zn[j] = __ldcs(gp);
                fn[j] = __ldcs(gp + HID / 2);
                gp += step2;
            }
        }
#pragma unroll
        for (int j = 0; j < SCH; j++) {
            float2 zv = __half22float2(zc[j]);
            float2 fv = __half22float2(fc[j]);
            float z0 = tanh_(zv.x + bz.x), z1 = tanh_(zv.y + bz.y);
            float f0 = sigm_(fv.x + bf.x), f1 = sigm_(fv.y + bf.y);
            hs0 = fmaf(f0, z0 - hs0, hs0);
            hs1 = fmaf(f1, z1 - hs1, hs1);
            A0 *= (1.0f - f0);
            A1 *= (1.0f - f1);
        }
#pragma unroll
        for (int j = 0; j < SCH; j++) { zc[j] = zn[j]; fc[j] = fn[j]; }
    }

    *(float2*)&g_A[c * NLANE + lane] = make_float2(A0, A1);
    *(float2*)&g_C[c * NLANE + lane] = make_float2(hs0, hs1);
}

__global__ __launch_bounds__(256) void scan_combine()
{
    const int lane = blockIdx.x * 256 + threadIdx.x;  // 0..16383
    float H = 0.0f;
#pragma unroll
    for (int c = 0; c < NCHK; c++) {
        g_Hin[c * NLANE + lane] = H;
        H = g_A[c * NLANE + lane] * H + g_C[c * NLANE + lane];
    }
}

__global__ __launch_bounds__(256) void scan_phase3(
    const float* __restrict__ bfw,
    const float* __restrict__ bbw,
    float* __restrict__ Y)
{
    const int t    = blockIdx.x * 256 + threadIdx.x;   // 0..65535
    const int h    = (t & 255) * 2;
    const int c    = (t >> 8) & 7;
    const int bi   = (t >> 11) & 15;
    const int dir  = t >> 15;
    const int lane = dir * 8192 + bi * 512 + h;

    const float* bias = dir ? bbw : bfw;
    const float2 bz = *(const float2*)(bias + h);
    const float2 bf = *(const float2*)(bias + HID + h);
    const float2 bo = *(const float2*)(bias + 2 * HID + h);

    const int s0 = dir ? (SEQ - 1 - c * CHLEN) : (c * CHLEN);
    const long long step2  = (dir ? -(long long)(BATCH * NCOLS)   : (long long)(BATCH * NCOLS)) / 2;
    const long long ystep2 = (dir ? -(long long)(BATCH * 2 * HID) : (long long)(BATCH * 2 * HID)) / 2;
    const __half2* gp = (const __half2*)(g_G + ((long long)(s0 * BATCH + bi)) * NCOLS
                                         + dir * 3 * HID + h);
    float2* yp = (float2*)(Y + ((long long)(s0 * BATCH + bi)) * (2 * HID) + dir * HID + h);

    __half2 zc[SCH], fc[SCH], oc[SCH];
#pragma unroll
    for (int j = 0; j < SCH; j++) {
        zc[j] = __ldcs(gp);
        fc[j] = __ldcs(gp + HID / 2);
        oc[j] = __ldcs(gp + HID);
        gp += step2;
    }

    float2 hin = *(const float2*)&g_Hin[c * NLANE + lane];
    float hs0 = hin.x, hs1 = hin.y;
    const int NIT = CHLEN / SCH;  // 32
    for (int it = 0; it < NIT; it++) {
        __half2 zn[SCH], fn[SCH], on[SCH];
        if (it < NIT - 1) {
#pragma unroll
            for (int j = 0; j < SCH; j++) {
                zn[j] = __ldcs(gp);
                fn[j] = __ldcs(gp + HID / 2);
                on[j] = __ldcs(gp + HID);
                gp += step2;
            }
        }
#pragma unroll
        for (int j = 0; j < SCH; j++) {
            float2 zv = __half22float2(zc[j]);
            float2 fv = __half22float2(fc[j]);
            float2 ov = __half22float2(oc[j]);
            float z0 = tanh_(zv.x + bz.x), z1 = tanh_(zv.y + bz.y);
            float f0 = sigm_(fv.x + bf.x), f1 = sigm_(fv.y + bf.y);
            float o0 = sigm_(ov.x + bo.x), o1 = sigm_(ov.y + bo.y);
            hs0 = fmaf(f0, z0 - hs0, hs0);
            hs1 = fmaf(f1, z1 - hs1, hs1);
            __stcs(yp, make_float2(o0 * hs0, o1 * hs1));
            yp += ystep2;
        }
#pragma unroll
        for (int j = 0; j < SCH; j++) { zc[j] = zn[j]; fc[j] = fn[j]; oc[j] = on[j]; }
    }
}

// ---------------------------------------------------------------------------
// Launch
// ---------------------------------------------------------------------------
extern "C" void kernel_launch(void* const* d_in, const int* in_sizes, int n_in,
                              void* d_out, int out_size)
{
    const float* X   = (const float*)d_in[0];
    const float* Wfw = (const float*)d_in[1];
    const float* bfw = (const float*)d_in[2];
    const float* Wbw = (const float*)d_in[3];
    const float* bbw = (const float*)d_in[4];
    float* Y = (float*)d_out;

    cudaFuncAttributes pa;
    bool use_tc = false;
    if (cudaFuncGetAttributes(&pa, probe_kernel) == cudaSuccess)
        use_tc = (pa.sharedSizeBytes >= 4096);

    cvt_kernel<<<17920, 256>>>(X, Wfw, Wbw);

    if (use_tc) {
        cudaFuncSetAttribute(gemm_tc_kernel, cudaFuncAttributeMaxDynamicSharedMemorySize, GEMM_SMEM);
        gemm_tc_kernel<<<GEMM_CTAS, GEMM_THREADS, GEMM_SMEM>>>();
    } else {
        dim3 ggrid(NCOLS / BN, MROWS / BM);   // (24, 256)
        gemm_fp16_kernel<<<ggrid, 256>>>();
    }

    scan_phase1<<<65536 / 256, 256>>>(bfw, bbw);
    scan_combine<<<16384 / 256, 256>>>();
    scan_phase3<<<65536 / 256, 256>>>(bfw, bbw, Y);
}